// round 2
// baseline (speedup 1.0000x reference)
#include <cuda_runtime.h>
#include <math.h>

#define N_TOK 16384
#define D_DIM 1024
#define E_NUM 16
#define H_DIM 4096
#define NC_DIM 1000
#define CAP 2048
#define NB_GATE (N_TOK/8)

// ---------------- device scratch (static globals: no allocation allowed) ----
__device__ float g_disp[(size_t)E_NUM*CAP*D_DIM];   // 128 MB dispatched tokens
__device__ float g_h[(size_t)E_NUM*CAP*H_DIM];      // 512 MB hidden acts
__device__ float g_oute[(size_t)E_NUM*CAP*D_DIM];   // 128 MB expert outputs
__device__ float g_y[(size_t)N_TOK*D_DIM];          // 64 MB combined tokens
__device__ int   g_idx[N_TOK];
__device__ float g_gate[N_TOK];
__device__ int   g_lrank[N_TOK];
__device__ int   g_bhist[NB_GATE][E_NUM];
__device__ int   g_boff[NB_GATE][E_NUM];
__device__ int   g_count[E_NUM];
__device__ float g_probsum[E_NUM];
__device__ int   g_pos[N_TOK];

// ---------------- init: zero the probability accumulators ------------------
__global__ void k_init() {
    if (threadIdx.x < E_NUM) g_probsum[threadIdx.x] = 0.f;
}

// ---------------- gating: logits, softmax, argmax, block hist/ranks --------
// one warp per token, 8 tokens per block
__global__ void k_gate(const float* __restrict__ x, const float* __restrict__ Wg) {
    int warp = threadIdx.x >> 5, lane = threadIdx.x & 31;
    int t = blockIdx.x * 8 + warp;

    __shared__ float s_prob[E_NUM];
    __shared__ int   s_idx[8];
    if (threadIdx.x < E_NUM) s_prob[threadIdx.x] = 0.f;
    __syncthreads();

    float acc[E_NUM];
#pragma unroll
    for (int e = 0; e < E_NUM; e++) acc[e] = 0.f;

    const float* xr = x + (size_t)t * D_DIM;
    for (int j = 0; j < D_DIM / 32; j++) {
        float xv = xr[lane + 32 * j];
        const float* wr = Wg + (size_t)(lane + 32 * j) * E_NUM;
#pragma unroll
        for (int e = 0; e < E_NUM; e++) acc[e] = fmaf(xv, __ldg(wr + e), acc[e]);
    }
#pragma unroll
    for (int e = 0; e < E_NUM; e++) {
#pragma unroll
        for (int o = 16; o > 0; o >>= 1) acc[e] += __shfl_xor_sync(0xffffffffu, acc[e], o);
    }

    if (lane == 0) {
        float m = acc[0]; int ai = 0;
#pragma unroll
        for (int e = 1; e < E_NUM; e++) if (acc[e] > m) { m = acc[e]; ai = e; }
        float p[E_NUM]; float s = 0.f;
#pragma unroll
        for (int e = 0; e < E_NUM; e++) { p[e] = expf(acc[e] - m); s += p[e]; }
        float inv = 1.f / s;
#pragma unroll
        for (int e = 0; e < E_NUM; e++) atomicAdd(&s_prob[e], p[e] * inv);
        g_idx[t] = ai;
        g_gate[t] = p[ai] * inv;
        s_idx[warp] = ai;
    }
    __syncthreads();

    if (threadIdx.x == 0) {
        int cnt[E_NUM];
#pragma unroll
        for (int e = 0; e < E_NUM; e++) cnt[e] = 0;
#pragma unroll
        for (int w = 0; w < 8; w++) {
            int e = s_idx[w];
            g_lrank[blockIdx.x * 8 + w] = cnt[e];
            cnt[e]++;
        }
#pragma unroll
        for (int e = 0; e < E_NUM; e++) g_bhist[blockIdx.x][e] = cnt[e];
    }
    if (threadIdx.x < E_NUM) atomicAdd(&g_probsum[threadIdx.x], s_prob[threadIdx.x]);
}

// ---------------- exclusive scan of block histograms per expert ------------
// grid = E_NUM blocks, 256 threads each; each thread handles 8 gate-blocks
__global__ void k_scan() {
    const int PB = NB_GATE / 256;  // 8
    int e = blockIdx.x, tid = threadIdx.x;
    int v[PB]; int s = 0;
#pragma unroll
    for (int i = 0; i < PB; i++) { v[i] = g_bhist[tid * PB + i][e]; s += v[i]; }

    __shared__ int sh[256];
    sh[tid] = s;
    __syncthreads();
    for (int o = 1; o < 256; o <<= 1) {
        int q = (tid >= o) ? sh[tid - o] : 0;
        __syncthreads();
        sh[tid] += q;
        __syncthreads();
    }
    int excl = sh[tid] - s;
    int off = excl;
#pragma unroll
    for (int i = 0; i < PB; i++) { g_boff[tid * PB + i][e] = off; off += v[i]; }
    if (tid == 255) g_count[e] = sh[255];
}

// ---------------- dispatch: scatter kept tokens into [E, CAP, D] -----------
__global__ void k_dispatch(const float* __restrict__ x) {
    int t = blockIdx.x;
    int e = g_idx[t];
    int pos = g_boff[t >> 3][e] + g_lrank[t];
    if (pos < CAP) {
        if (threadIdx.x == 0) g_pos[t] = pos;
        const float4* src = (const float4*)(x + (size_t)t * D_DIM);
        float4* dst = (float4*)(g_disp + ((size_t)e * CAP + pos) * D_DIM);
        dst[threadIdx.x] = src[threadIdx.x];  // 256 threads x float4 = 1024 floats
    } else if (threadIdx.x == 0) {
        g_pos[t] = -1;
    }
}

// ---------------- SGEMM 128x128x8, 8x8 per thread, bias + optional gelu ----
__device__ __forceinline__ float gelu_tanh(float v) {
    float c = 0.7978845608028654f;
    float u = c * (v + 0.044715f * v * v * v);
    return 0.5f * v * (1.f + tanhf(u));
}

template <int ACT, bool NBOUND>
__global__ __launch_bounds__(256) void k_gemm(
    const float* __restrict__ A, const float* __restrict__ Bm,
    const float* __restrict__ bias, float* __restrict__ Cm,
    int Nn, int K,
    size_t strideAe, size_t strideBe, size_t strideBiasE, size_t strideCe,
    const int* __restrict__ cnt)
{
    int e = blockIdx.z;
    if (cnt) {
        int c = cnt[e]; if (c > CAP) c = CAP;
        if ((int)blockIdx.y * 128 >= c) return;  // skip tiles past expert count
    }
    A  += (size_t)e * strideAe;
    Bm += (size_t)e * strideBe;
    Cm += (size_t)e * strideCe;
    bias += (size_t)e * strideBiasE;

    __shared__ float As[8][128];
    __shared__ float Bs[8][128];

    int tid = threadIdx.x;
    int brow = blockIdx.y * 128, bcol = blockIdx.x * 128;
    int aRow = tid >> 1, aCol = (tid & 1) * 4;
    int bRow = tid >> 5, bCol = (tid & 31) * 4;
    int tx = tid & 15, ty = tid >> 4;

    float accv[8][8];
#pragma unroll
    for (int i = 0; i < 8; i++)
#pragma unroll
        for (int j = 0; j < 8; j++) accv[i][j] = 0.f;

    const float* Aptr = A + (size_t)(brow + aRow) * K + aCol;
    const float* Bptr = Bm + (size_t)bRow * Nn + bcol + bCol;

    for (int k0 = 0; k0 < K; k0 += 8) {
        float4 a4 = *(const float4*)Aptr;
        As[aCol + 0][aRow] = a4.x;
        As[aCol + 1][aRow] = a4.y;
        As[aCol + 2][aRow] = a4.z;
        As[aCol + 3][aRow] = a4.w;
        float4 b4;
        if (NBOUND) {
            int cbase = bcol + bCol;
            b4.x = (cbase + 0 < Nn) ? Bptr[0] : 0.f;
            b4.y = (cbase + 1 < Nn) ? Bptr[1] : 0.f;
            b4.z = (cbase + 2 < Nn) ? Bptr[2] : 0.f;
            b4.w = (cbase + 3 < Nn) ? Bptr[3] : 0.f;
        } else {
            b4 = *(const float4*)Bptr;
        }
        Bs[bRow][bCol + 0] = b4.x;
        Bs[bRow][bCol + 1] = b4.y;
        Bs[bRow][bCol + 2] = b4.z;
        Bs[bRow][bCol + 3] = b4.w;
        __syncthreads();

#pragma unroll
        for (int k = 0; k < 8; k++) {
            float ra[8], rb[8];
#pragma unroll
            for (int i = 0; i < 8; i++) ra[i] = As[k][ty * 8 + i];
#pragma unroll
            for (int j = 0; j < 8; j++) rb[j] = Bs[k][tx * 8 + j];
#pragma unroll
            for (int i = 0; i < 8; i++)
#pragma unroll
                for (int j = 0; j < 8; j++) accv[i][j] = fmaf(ra[i], rb[j], accv[i][j]);
        }
        __syncthreads();
        Aptr += 8;
        Bptr += (size_t)8 * Nn;
    }

#pragma unroll
    for (int i = 0; i < 8; i++) {
        int row = brow + ty * 8 + i;
#pragma unroll
        for (int j = 0; j < 8; j++) {
            int col = bcol + tx * 8 + j;
            if (!NBOUND || col < Nn) {
                float v = accv[i][j] + bias[col];
                if (ACT == 1) v = gelu_tanh(v);
                Cm[(size_t)row * Nn + col] = v;
            }
        }
    }
}

// ---------------- combine: gather expert outputs, scale by gate ------------
__global__ void k_combine() {
    int t = blockIdx.x;
    int pos = g_pos[t];
    float4* dst = (float4*)(g_y + (size_t)t * D_DIM);
    if (pos >= 0) {
        int e = g_idx[t];
        float g = g_gate[t];
        const float4* src = (const float4*)(g_oute + ((size_t)e * CAP + pos) * D_DIM);
        float4 v = src[threadIdx.x];
        v.x *= g; v.y *= g; v.z *= g; v.w *= g;
        dst[threadIdx.x] = v;
    } else {
        dst[threadIdx.x] = make_float4(0.f, 0.f, 0.f, 0.f);
    }
}

// ---------------- balancing loss --------------------------------------------
__global__ void k_loss(float* out, int out_size) {
    if (out_size <= N_TOK * NC_DIM) return;
    if (threadIdx.x == 0 && blockIdx.x == 0) {
        float s = 0.f;
        for (int e = 0; e < E_NUM; e++)
            s += ((float)g_count[e] / (float)N_TOK) * (g_probsum[e] / (float)N_TOK);
        out[(size_t)N_TOK * NC_DIM] = s * (float)E_NUM;
    }
}

// ---------------- launch -----------------------------------------------------
extern "C" void kernel_launch(void* const* d_in, const int* in_sizes, int n_in,
                              void* d_out, int out_size) {
    const float* x  = (const float*)d_in[0];
    const float* Wg = (const float*)d_in[1];
    const float* W1 = (const float*)d_in[2];
    const float* b1 = (const float*)d_in[3];
    const float* W2 = (const float*)d_in[4];
    const float* b2 = (const float*)d_in[5];
    const float* Wl = (const float*)d_in[6];
    const float* bl = (const float*)d_in[7];
    float* out = (float*)d_out;

    void *p_disp, *p_h, *p_oute, *p_y, *p_cnt;
    cudaGetSymbolAddress(&p_disp, g_disp);
    cudaGetSymbolAddress(&p_h, g_h);
    cudaGetSymbolAddress(&p_oute, g_oute);
    cudaGetSymbolAddress(&p_y, g_y);
    cudaGetSymbolAddress(&p_cnt, g_count);

    k_init<<<1, 32>>>();
    k_gate<<<NB_GATE, 256>>>(x, Wg);
    k_scan<<<E_NUM, 256>>>();
    k_dispatch<<<N_TOK, 256>>>(x);

    // FFN1: [CAP,1024] @ [1024,4096] + b1, gelu  (per expert, tile-skipped by count)
    {
        dim3 grid(H_DIM / 128, CAP / 128, E_NUM);
        k_gemm<1, false><<<grid, 256>>>(
            (const float*)p_disp, W1, b1, (float*)p_h,
            H_DIM, D_DIM,
            (size_t)CAP * D_DIM, (size_t)D_DIM * H_DIM, (size_t)H_DIM, (size_t)CAP * H_DIM,
            (const int*)p_cnt);
    }
    // FFN2: [CAP,4096] @ [4096,1024] + b2
    {
        dim3 grid(D_DIM / 128, CAP / 128, E_NUM);
        k_gemm<0, false><<<grid, 256>>>(
            (const float*)p_h, W2, b2, (float*)p_oute,
            D_DIM, H_DIM,
            (size_t)CAP * H_DIM, (size_t)H_DIM * D_DIM, (size_t)D_DIM, (size_t)CAP * D_DIM,
            (const int*)p_cnt);
    }

    k_combine<<<N_TOK, 256>>>();

    // classifier: [16384,1024] @ [1024,1000] + bl  -> out
    {
        dim3 grid((NC_DIM + 127) / 128, N_TOK / 128, 1);
        k_gemm<0, true><<<grid, 256>>>(
            (const float*)p_y, Wl, bl, out,
            NC_DIM, D_DIM,
            0, 0, 0, 0,
            nullptr);
    }

    k_loss<<<1, 32>>>(out, out_size);
}

// round 4
// speedup vs baseline: 2.6156x; 2.6156x over previous
#include <cuda_runtime.h>
#include <cuda_bf16.h>
#include <math.h>
#include <stdint.h>

#define N_TOK 16384
#define D_DIM 1024
#define E_NUM 16
#define H_DIM 4096
#define NC_DIM 1000
#define CAP 2048
#define NB_GATE (N_TOK/8)

typedef __nv_bfloat16 bf16;

// ---------------- device scratch ----------------
__device__ __align__(16) bf16 g_disp_hi[(size_t)E_NUM*CAP*D_DIM];
__device__ __align__(16) bf16 g_disp_lo[(size_t)E_NUM*CAP*D_DIM];
__device__ __align__(16) bf16 g_h_hi[(size_t)E_NUM*CAP*H_DIM];
__device__ __align__(16) bf16 g_h_lo[(size_t)E_NUM*CAP*H_DIM];
__device__ __align__(16) float g_oute[(size_t)E_NUM*CAP*D_DIM];
__device__ __align__(16) bf16 g_y_hi[(size_t)N_TOK*D_DIM];
__device__ __align__(16) bf16 g_y_lo[(size_t)N_TOK*D_DIM];
__device__ __align__(16) bf16 g_w1t_hi[(size_t)E_NUM*H_DIM*D_DIM];
__device__ __align__(16) bf16 g_w1t_lo[(size_t)E_NUM*H_DIM*D_DIM];
__device__ __align__(16) bf16 g_w2t_hi[(size_t)E_NUM*D_DIM*H_DIM];
__device__ __align__(16) bf16 g_w2t_lo[(size_t)E_NUM*D_DIM*H_DIM];
__device__ __align__(16) bf16 g_wlt_hi[(size_t)1024*D_DIM];
__device__ __align__(16) bf16 g_wlt_lo[(size_t)1024*D_DIM];
__device__ int   g_idx[N_TOK];
__device__ float g_gate[N_TOK];
__device__ int   g_lrank[N_TOK];
__device__ int   g_bhist[NB_GATE][E_NUM];
__device__ int   g_boff[NB_GATE][E_NUM];
__device__ int   g_count[E_NUM];
__device__ float g_probsum[E_NUM];
__device__ int   g_pos[N_TOK];

// ---------------- PTX helpers (sm_80-compatible only) ----------------
__device__ __forceinline__ uint32_t smem_u32(const void* p) {
    return (uint32_t)__cvta_generic_to_shared(p);
}
__device__ __forceinline__ void cpa(uint32_t dst, const void* src) {
    asm volatile("cp.async.cg.shared.global [%0], [%1], 16;" :: "r"(dst), "l"(src) : "memory");
}
__device__ __forceinline__ void cpa_commit() { asm volatile("cp.async.commit_group;" ::: "memory"); }
template<int N> __device__ __forceinline__ void cpa_wait() {
    asm volatile("cp.async.wait_group %0;" :: "n"(N) : "memory");
}
__device__ __forceinline__ void ldsm4(uint32_t* r, uint32_t a) {
    asm volatile("ldmatrix.sync.aligned.m8n8.x4.shared.b16 {%0,%1,%2,%3}, [%4];"
                 : "=r"(r[0]), "=r"(r[1]), "=r"(r[2]), "=r"(r[3]) : "r"(a));
}
__device__ __forceinline__ void ldsm2(uint32_t* r, uint32_t a) {
    asm volatile("ldmatrix.sync.aligned.m8n8.x2.shared.b16 {%0,%1}, [%2];"
                 : "=r"(r[0]), "=r"(r[1]) : "r"(a));
}
__device__ __forceinline__ void mma_bf16(float* d, const uint32_t* a, const uint32_t* b) {
    asm volatile(
        "mma.sync.aligned.m16n8k16.row.col.f32.bf16.bf16.f32 "
        "{%0,%1,%2,%3}, {%4,%5,%6,%7}, {%8,%9}, {%0,%1,%2,%3};"
        : "+f"(d[0]), "+f"(d[1]), "+f"(d[2]), "+f"(d[3])
        : "r"(a[0]), "r"(a[1]), "r"(a[2]), "r"(a[3]), "r"(b[0]), "r"(b[1]));
}

// ---------------- routing ----------------
__global__ void k_init() { if (threadIdx.x < E_NUM) g_probsum[threadIdx.x] = 0.f; }

__global__ void k_gate(const float* __restrict__ x, const float* __restrict__ Wg) {
    int warp = threadIdx.x >> 5, lane = threadIdx.x & 31;
    int t = blockIdx.x * 8 + warp;
    __shared__ float s_prob[E_NUM];
    __shared__ int s_idx[8];
    if (threadIdx.x < E_NUM) s_prob[threadIdx.x] = 0.f;
    __syncthreads();
    float acc[E_NUM];
#pragma unroll
    for (int e = 0; e < E_NUM; e++) acc[e] = 0.f;
    const float* xr = x + (size_t)t * D_DIM;
    for (int j = 0; j < D_DIM / 32; j++) {
        float xv = xr[lane + 32 * j];
        const float* wr = Wg + (size_t)(lane + 32 * j) * E_NUM;
#pragma unroll
        for (int e = 0; e < E_NUM; e++) acc[e] = fmaf(xv, __ldg(wr + e), acc[e]);
    }
#pragma unroll
    for (int e = 0; e < E_NUM; e++)
#pragma unroll
        for (int o = 16; o > 0; o >>= 1) acc[e] += __shfl_xor_sync(0xffffffffu, acc[e], o);
    if (lane == 0) {
        float m = acc[0]; int ai = 0;
#pragma unroll
        for (int e = 1; e < E_NUM; e++) if (acc[e] > m) { m = acc[e]; ai = e; }
        float p[E_NUM]; float s = 0.f;
#pragma unroll
        for (int e = 0; e < E_NUM; e++) { p[e] = expf(acc[e] - m); s += p[e]; }
        float inv = 1.f / s;
#pragma unroll
        for (int e = 0; e < E_NUM; e++) atomicAdd(&s_prob[e], p[e] * inv);
        g_idx[t] = ai; g_gate[t] = p[ai] * inv; s_idx[warp] = ai;
    }
    __syncthreads();
    if (threadIdx.x == 0) {
        int cnt[E_NUM];
#pragma unroll
        for (int e = 0; e < E_NUM; e++) cnt[e] = 0;
#pragma unroll
        for (int w = 0; w < 8; w++) {
            int e = s_idx[w];
            g_lrank[blockIdx.x * 8 + w] = cnt[e];
            cnt[e]++;
        }
#pragma unroll
        for (int e = 0; e < E_NUM; e++) g_bhist[blockIdx.x][e] = cnt[e];
    }
    if (threadIdx.x < E_NUM) atomicAdd(&g_probsum[threadIdx.x], s_prob[threadIdx.x]);
}

__global__ void k_scan() {
    const int PB = NB_GATE / 256;
    int e = blockIdx.x, tid = threadIdx.x;
    int v[PB]; int s = 0;
#pragma unroll
    for (int i = 0; i < PB; i++) { v[i] = g_bhist[tid * PB + i][e]; s += v[i]; }
    __shared__ int sh[256];
    sh[tid] = s; __syncthreads();
    for (int o = 1; o < 256; o <<= 1) {
        int q = (tid >= o) ? sh[tid - o] : 0;
        __syncthreads(); sh[tid] += q; __syncthreads();
    }
    int off = sh[tid] - s;
#pragma unroll
    for (int i = 0; i < PB; i++) { g_boff[tid * PB + i][e] = off; off += v[i]; }
    if (tid == 255) g_count[e] = sh[255];
}

__device__ __forceinline__ void split2(float a, float b, bf16* hi, bf16* lo) {
    bf16 ha = __float2bfloat16(a), hb = __float2bfloat16(b);
    *(__nv_bfloat162*)hi = __halves2bfloat162(ha, hb);
    *(__nv_bfloat162*)lo = __halves2bfloat162(
        __float2bfloat16(a - __bfloat162float(ha)),
        __float2bfloat16(b - __bfloat162float(hb)));
}

__global__ void k_dispatch(const float* __restrict__ x) {
    int t = blockIdx.x;
    int e = g_idx[t];
    int pos = g_boff[t >> 3][e] + g_lrank[t];
    if (pos < CAP) {
        if (threadIdx.x == 0) g_pos[t] = pos;
        float4 v = ((const float4*)(x + (size_t)t * D_DIM))[threadIdx.x];
        size_t b = ((size_t)e * CAP + pos) * D_DIM + threadIdx.x * 4;
        split2(v.x, v.y, g_disp_hi + b, g_disp_lo + b);
        split2(v.z, v.w, g_disp_hi + b + 2, g_disp_lo + b + 2);
    } else if (threadIdx.x == 0) g_pos[t] = -1;
}

__global__ void k_pad() {
    int e = blockIdx.x;
    int c = g_count[e]; if (c > CAP) c = CAP;
    int r1 = (c + 127) & ~127; if (r1 > CAP) r1 = CAP;
    for (int r = c; r < r1; r++) {
        size_t b = ((size_t)e * CAP + r) * D_DIM + threadIdx.x * 4;
        *(float2*)(g_disp_hi + b) = make_float2(0.f, 0.f);
        *(float2*)(g_disp_lo + b) = make_float2(0.f, 0.f);
    }
}

// transpose+split: in [E,R,C] fp32 -> out [E,Cpad,R] bf16 hi/lo
__global__ void k_wsplit(const float* __restrict__ in, bf16* __restrict__ ohi,
                         bf16* __restrict__ olo, int R, int C, int Cpad) {
    __shared__ float s[32][33];
    int e = blockIdx.z;
    const float* ip = in + (size_t)e * R * C;
    size_t ob = (size_t)e * Cpad * R;
    int c0 = blockIdx.x * 32, r0 = blockIdx.y * 32;
    int tx = threadIdx.x, ty = threadIdx.y;
#pragma unroll
    for (int k = 0; k < 4; k++) {
        int r = r0 + ty + 8 * k, c = c0 + tx;
        s[ty + 8 * k][tx] = (c < C) ? ip[(size_t)r * C + c] : 0.f;
    }
    __syncthreads();
#pragma unroll
    for (int k = 0; k < 4; k++) {
        int cc = ty + 8 * k;
        float v = s[tx][cc];
        bf16 h = __float2bfloat16(v);
        size_t o = ob + (size_t)(c0 + cc) * R + r0 + tx;
        ohi[o] = h;
        olo[o] = __float2bfloat16(v - __bfloat162float(h));
    }
}

__global__ void k_combine() {
    int t = blockIdx.x;
    int pos = g_pos[t];
    size_t b = (size_t)t * D_DIM + threadIdx.x * 4;
    if (pos >= 0) {
        int e = g_idx[t];
        float g = g_gate[t];
        float4 v = ((const float4*)(g_oute + ((size_t)e * CAP + pos) * D_DIM))[threadIdx.x];
        split2(v.x * g, v.y * g, g_y_hi + b, g_y_lo + b);
        split2(v.z * g, v.w * g, g_y_hi + b + 2, g_y_lo + b + 2);
    } else {
        *(float2*)(g_y_hi + b) = make_float2(0.f, 0.f);
        *(float2*)(g_y_lo + b) = make_float2(0.f, 0.f);
    }
}

__global__ void k_loss(float* out, int out_size) {
    if (out_size <= N_TOK * NC_DIM) return;
    if (threadIdx.x == 0 && blockIdx.x == 0) {
        float s = 0.f;
        for (int e = 0; e < E_NUM; e++)
            s += ((float)g_count[e] / (float)N_TOK) * (g_probsum[e] / (float)N_TOK);
        out[(size_t)N_TOK * NC_DIM] = s * (float)E_NUM;
    }
}

// ---------------- mma.sync bf16 GEMM: CTA 128x128, BK=64, 3-stage ----------
// A [M,K] row-major bf16 (hi,lo), B [N,K] row-major bf16 (hi,lo)
// C = Ahi*Bhi^T + Ahi*Blo^T + Alo*Bhi^T (fp32 accum)
// MODE 0: FFN1 (bias+gelu -> bf16 hi/lo), MODE 1: FFN2 (bias -> f32),
// MODE 2: classifier (bias -> f32, col < colmax)
#define STG_B 65536
#define OFF_ALO 16384
#define OFF_BHI 32768
#define OFF_BLO 49152
#define GEMM_SMEM (3*STG_B + 128)

__device__ __forceinline__ float gelu_tanh(float v) {
    float u = 0.7978845608028654f * (v + 0.044715f * v * v * v);
    return 0.5f * v * (1.f + tanhf(u));
}
__device__ __forceinline__ uint32_t swz(int row, int c) {
    return (uint32_t)(row * 128 + ((c ^ (row & 7)) << 4));
}

template <int MODE>
__global__ void __launch_bounds__(256, 1) k_mgemm(
    const bf16* __restrict__ Ahi, const bf16* __restrict__ Alo, size_t sAe,
    const bf16* __restrict__ Bhi, const bf16* __restrict__ Blo, size_t sBe,
    const float* __restrict__ bias, int sBiasE,
    void* __restrict__ out0, void* __restrict__ out1, size_t sCe,
    int K, int ldc, int colmax)
{
    int e = blockIdx.z;
    int m0 = blockIdx.y * 128, n0 = blockIdx.x * 128;
    if (MODE < 2) {
        int c = g_count[e]; if (c > CAP) c = CAP;
        if (m0 >= c) return;
    }
    Ahi += (size_t)e * sAe; Alo += (size_t)e * sAe;
    Bhi += (size_t)e * sBe; Blo += (size_t)e * sBe;
    bias += (size_t)e * sBiasE;

    extern __shared__ char smem_raw[];
    uint32_t base = (smem_u32(smem_raw) + 127) & ~127u;

    int tid = threadIdx.x, lane = tid & 31, wid = tid >> 5;
    int wr = wid >> 2, wc = wid & 3;   // warp 64x32 tile at (wr*64, wc*32)

    float acc[4][4][4];
#pragma unroll
    for (int i = 0; i < 4; i++)
#pragma unroll
        for (int j = 0; j < 4; j++)
#pragma unroll
            for (int q = 0; q < 4; q++) acc[i][j][q] = 0.f;

    int nch = K >> 6;

    // loader: 4 iters/thread; each iter covers (Ahi,Alo,Bhi,Blo) same (row,c)
    auto load_chunk = [&](int s, int c) {
        uint32_t stg = base + s * STG_B;
        int k0 = c << 6;
#pragma unroll
        for (int it = 0; it < 4; it++) {
            int i = tid + it * 256;        // 0..1023
            int row = i >> 3, cc = i & 7;
            uint32_t o = swz(row, cc);
            const bf16* a = Ahi + (size_t)(m0 + row) * K + k0 + cc * 8;
            const bf16* al = Alo + (size_t)(m0 + row) * K + k0 + cc * 8;
            const bf16* b = Bhi + (size_t)(n0 + row) * K + k0 + cc * 8;
            const bf16* bl = Blo + (size_t)(n0 + row) * K + k0 + cc * 8;
            cpa(stg + o, a);
            cpa(stg + OFF_ALO + o, al);
            cpa(stg + OFF_BHI + o, b);
            cpa(stg + OFF_BLO + o, bl);
        }
    };

    load_chunk(0, 0); cpa_commit();
    load_chunk(1, 1); cpa_commit();
    load_chunk(2, 2); cpa_commit();

    for (int c = 0; c < nch; c++) {
        int s = c - (c / 3) * 3;
        uint32_t stg = base + s * STG_B;
        cpa_wait<2>();
        __syncthreads();

#pragma unroll
        for (int ks = 0; ks < 4; ks++) {
            uint32_t ah[4][4], al[4][4], bh[4][2], bl[4][2];
            int ar = wr * 64 + (lane & 15);
            int ac = ks * 2 + (lane >> 4);
#pragma unroll
            for (int i = 0; i < 4; i++) {
                int r = ar + i * 16;
                uint32_t adr = stg + swz(r, ac);
                ldsm4(ah[i], adr);
                ldsm4(al[i], adr + OFF_ALO);
            }
            int br = wc * 32 + (lane & 7);
            int bc = ks * 2 + ((lane >> 3) & 1);
#pragma unroll
            for (int j = 0; j < 4; j++) {
                int r = br + j * 8;
                uint32_t adr = stg + OFF_BHI + swz(r, bc);
                ldsm2(bh[j], adr);
                ldsm2(bl[j], adr + 16384);
            }
#pragma unroll
            for (int i = 0; i < 4; i++)
#pragma unroll
                for (int j = 0; j < 4; j++) {
                    mma_bf16(acc[i][j], ah[i], bh[j]);
                    mma_bf16(acc[i][j], ah[i], bl[j]);
                    mma_bf16(acc[i][j], al[i], bh[j]);
                }
        }
        __syncthreads();
        if (c + 3 < nch) load_chunk(s, c + 3);
        cpa_commit();
    }

    // epilogue
    int rb = m0 + wr * 64, cb = n0 + wc * 32;
#pragma unroll
    for (int i = 0; i < 4; i++)
#pragma unroll
        for (int j = 0; j < 4; j++) {
            int r0 = rb + i * 16 + (lane >> 2);
            int c0 = cb + j * 8 + (lane & 3) * 2;
            float bx = bias[c0], by = bias[c0 + 1];
#pragma unroll
            for (int h = 0; h < 2; h++) {
                int row = r0 + h * 8;
                float v0 = acc[i][j][h * 2 + 0] + bx;
                float v1 = acc[i][j][h * 2 + 1] + by;
                size_t o = (size_t)e * sCe + (size_t)row * ldc + c0;
                if (MODE == 0) {
                    v0 = gelu_tanh(v0); v1 = gelu_tanh(v1);
                    split2(v0, v1, (bf16*)out0 + o, (bf16*)out1 + o);
                } else if (MODE == 1) {
                    *(float2*)((float*)out0 + o) = make_float2(v0, v1);
                } else {
                    size_t oo = (size_t)row * ldc + c0;
                    if (c0 < colmax)     ((float*)out0)[oo] = v0;
                    if (c0 + 1 < colmax) ((float*)out0)[oo + 1] = v1;
                }
            }
        }
}

// ---------------- launch ----------------
extern "C" void kernel_launch(void* const* d_in, const int* in_sizes, int n_in,
                              void* d_out, int out_size) {
    const float* x  = (const float*)d_in[0];
    const float* Wg = (const float*)d_in[1];
    const float* W1 = (const float*)d_in[2];
    const float* b1 = (const float*)d_in[3];
    const float* W2 = (const float*)d_in[4];
    const float* b2 = (const float*)d_in[5];
    const float* Wl = (const float*)d_in[6];
    const float* bl = (const float*)d_in[7];
    float* out = (float*)d_out;

    static int smem_set = 0;
    if (!smem_set) {
        cudaFuncSetAttribute(k_mgemm<0>, cudaFuncAttributeMaxDynamicSharedMemorySize, GEMM_SMEM);
        cudaFuncSetAttribute(k_mgemm<1>, cudaFuncAttributeMaxDynamicSharedMemorySize, GEMM_SMEM);
        cudaFuncSetAttribute(k_mgemm<2>, cudaFuncAttributeMaxDynamicSharedMemorySize, GEMM_SMEM);
        smem_set = 1;
    }

    bf16 *w1h, *w1l, *w2h, *w2l, *wlh, *wll, *dh, *dl, *hh, *hl, *yh, *yl;
    float* oute;
    cudaGetSymbolAddress((void**)&w1h, g_w1t_hi); cudaGetSymbolAddress((void**)&w1l, g_w1t_lo);
    cudaGetSymbolAddress((void**)&w2h, g_w2t_hi); cudaGetSymbolAddress((void**)&w2l, g_w2t_lo);
    cudaGetSymbolAddress((void**)&wlh, g_wlt_hi); cudaGetSymbolAddress((void**)&wll, g_wlt_lo);
    cudaGetSymbolAddress((void**)&dh, g_disp_hi); cudaGetSymbolAddress((void**)&dl, g_disp_lo);
    cudaGetSymbolAddress((void**)&hh, g_h_hi);    cudaGetSymbolAddress((void**)&hl, g_h_lo);
    cudaGetSymbolAddress((void**)&yh, g_y_hi);    cudaGetSymbolAddress((void**)&yl, g_y_lo);
    cudaGetSymbolAddress((void**)&oute, g_oute);

    k_init<<<1, 32>>>();
    k_gate<<<NB_GATE, 256>>>(x, Wg);
    k_scan<<<E_NUM, 256>>>();
    k_dispatch<<<N_TOK, 256>>>(x);
    k_pad<<<E_NUM, 256>>>();

    dim3 tb(32, 8);
    k_wsplit<<<dim3(H_DIM/32, D_DIM/32, E_NUM), tb>>>(W1, w1h, w1l, D_DIM, H_DIM, H_DIM);
    k_wsplit<<<dim3(D_DIM/32, H_DIM/32, E_NUM), tb>>>(W2, w2h, w2l, H_DIM, D_DIM, D_DIM);
    k_wsplit<<<dim3(1024/32, D_DIM/32, 1), tb>>>(Wl, wlh, wll, D_DIM, NC_DIM, 1024);

    // FFN1: [CAP,1024] x [4096,1024]^T -> h [CAP,4096] bf16 hi/lo, gelu
    k_mgemm<0><<<dim3(H_DIM/128, CAP/128, E_NUM), 256, GEMM_SMEM>>>(
        dh, dl, (size_t)CAP*D_DIM, w1h, w1l, (size_t)H_DIM*D_DIM,
        b1, H_DIM, hh, hl, (size_t)CAP*H_DIM, D_DIM, H_DIM, H_DIM);
    // FFN2: [CAP,4096] x [1024,4096]^T -> oute [CAP,1024] f32
    k_mgemm<1><<<dim3(D_DIM/128, CAP/128, E_NUM), 256, GEMM_SMEM>>>(
        hh, hl, (size_t)CAP*H_DIM, w2h, w2l, (size_t)D_DIM*H_DIM,
        b2, D_DIM, oute, nullptr, (size_t)CAP*D_DIM, H_DIM, D_DIM, D_DIM);

    k_combine<<<N_TOK, 256>>>();

    // classifier: [16384,1024] x [1024(pad),1024]^T -> out [16384,1000]
    k_mgemm<2><<<dim3(1024/128, N_TOK/128, 1), 256, GEMM_SMEM>>>(
        yh, yl, 0, wlh, wll, 0,
        bl, 0, out, nullptr, 0, D_DIM, NC_DIM, NC_DIM);

    k_loss<<<1, 32>>>(out, out_size);
}

// round 5
// speedup vs baseline: 2.6493x; 1.0129x over previous
#include <cuda_runtime.h>
#include <cuda_bf16.h>
#include <math.h>
#include <stdint.h>

#define N_TOK 16384
#define D_DIM 1024
#define E_NUM 16
#define H_DIM 4096
#define NC_DIM 1000
#define CAP 2048
#define NB_GATE (N_TOK/8)

typedef __nv_bfloat16 bf16;

// ---------------- device scratch ----------------
__device__ __align__(16) bf16 g_disp_hi[(size_t)E_NUM*CAP*D_DIM];
__device__ __align__(16) bf16 g_disp_lo[(size_t)E_NUM*CAP*D_DIM];
__device__ __align__(16) bf16 g_h_hi[(size_t)E_NUM*CAP*H_DIM];
__device__ __align__(16) bf16 g_h_lo[(size_t)E_NUM*CAP*H_DIM];
__device__ __align__(16) float g_oute[(size_t)E_NUM*CAP*D_DIM];
__device__ __align__(16) bf16 g_y_hi[(size_t)N_TOK*D_DIM];
__device__ __align__(16) bf16 g_y_lo[(size_t)N_TOK*D_DIM];
__device__ __align__(16) bf16 g_w1t_hi[(size_t)E_NUM*H_DIM*D_DIM];
__device__ __align__(16) bf16 g_w1t_lo[(size_t)E_NUM*H_DIM*D_DIM];
__device__ __align__(16) bf16 g_w2t_hi[(size_t)E_NUM*D_DIM*H_DIM];
__device__ __align__(16) bf16 g_w2t_lo[(size_t)E_NUM*D_DIM*H_DIM];
__device__ __align__(16) bf16 g_wlt_hi[(size_t)1024*D_DIM];
__device__ __align__(16) bf16 g_wlt_lo[(size_t)1024*D_DIM];
__device__ int   g_idx[N_TOK];
__device__ float g_gate[N_TOK];
__device__ int   g_lrank[N_TOK];
__device__ int   g_bhist[NB_GATE][E_NUM];
__device__ int   g_boff[NB_GATE][E_NUM];
__device__ int   g_count[E_NUM];
__device__ float g_probsum[E_NUM];
__device__ int   g_pos[N_TOK];

// ---------------- PTX helpers (sm_80-compatible only) ----------------
__device__ __forceinline__ uint32_t smem_u32(const void* p) {
    return (uint32_t)__cvta_generic_to_shared(p);
}
__device__ __forceinline__ void cpa(uint32_t dst, const void* src) {
    asm volatile("cp.async.cg.shared.global [%0], [%1], 16;" :: "r"(dst), "l"(src) : "memory");
}
__device__ __forceinline__ void cpa_commit() { asm volatile("cp.async.commit_group;" ::: "memory"); }
template<int N> __device__ __forceinline__ void cpa_wait() {
    asm volatile("cp.async.wait_group %0;" :: "n"(N) : "memory");
}
__device__ __forceinline__ void ldsm4(uint32_t* r, uint32_t a) {
    asm volatile("ldmatrix.sync.aligned.m8n8.x4.shared.b16 {%0,%1,%2,%3}, [%4];"
                 : "=r"(r[0]), "=r"(r[1]), "=r"(r[2]), "=r"(r[3]) : "r"(a));
}
__device__ __forceinline__ void ldsm2(uint32_t* r, uint32_t a) {
    asm volatile("ldmatrix.sync.aligned.m8n8.x2.shared.b16 {%0,%1}, [%2];"
                 : "=r"(r[0]), "=r"(r[1]) : "r"(a));
}
__device__ __forceinline__ void mma_bf16(float* d, const uint32_t* a, const uint32_t* b) {
    asm volatile(
        "mma.sync.aligned.m16n8k16.row.col.f32.bf16.bf16.f32 "
        "{%0,%1,%2,%3}, {%4,%5,%6,%7}, {%8,%9}, {%0,%1,%2,%3};"
        : "+f"(d[0]), "+f"(d[1]), "+f"(d[2]), "+f"(d[3])
        : "r"(a[0]), "r"(a[1]), "r"(a[2]), "r"(a[3]), "r"(b[0]), "r"(b[1]));
}

// ---------------- routing ----------------
__global__ void k_init() { if (threadIdx.x < E_NUM) g_probsum[threadIdx.x] = 0.f; }

__global__ void k_gate(const float* __restrict__ x, const float* __restrict__ Wg) {
    int warp = threadIdx.x >> 5, lane = threadIdx.x & 31;
    int t = blockIdx.x * 8 + warp;
    __shared__ float s_prob[E_NUM];
    __shared__ int s_idx[8];
    if (threadIdx.x < E_NUM) s_prob[threadIdx.x] = 0.f;
    __syncthreads();
    float acc[E_NUM];
#pragma unroll
    for (int e = 0; e < E_NUM; e++) acc[e] = 0.f;
    const float* xr = x + (size_t)t * D_DIM;
    for (int j = 0; j < D_DIM / 32; j++) {
        float xv = xr[lane + 32 * j];
        const float* wr = Wg + (size_t)(lane + 32 * j) * E_NUM;
#pragma unroll
        for (int e = 0; e < E_NUM; e++) acc[e] = fmaf(xv, __ldg(wr + e), acc[e]);
    }
#pragma unroll
    for (int e = 0; e < E_NUM; e++)
#pragma unroll
        for (int o = 16; o > 0; o >>= 1) acc[e] += __shfl_xor_sync(0xffffffffu, acc[e], o);
    if (lane == 0) {
        float m = acc[0]; int ai = 0;
#pragma unroll
        for (int e = 1; e < E_NUM; e++) if (acc[e] > m) { m = acc[e]; ai = e; }
        float p[E_NUM]; float s = 0.f;
#pragma unroll
        for (int e = 0; e < E_NUM; e++) { p[e] = expf(acc[e] - m); s += p[e]; }
        float inv = 1.f / s;
#pragma unroll
        for (int e = 0; e < E_NUM; e++) atomicAdd(&s_prob[e], p[e] * inv);
        g_idx[t] = ai; g_gate[t] = p[ai] * inv; s_idx[warp] = ai;
    }
    __syncthreads();
    if (threadIdx.x == 0) {
        int cnt[E_NUM];
#pragma unroll
        for (int e = 0; e < E_NUM; e++) cnt[e] = 0;
#pragma unroll
        for (int w = 0; w < 8; w++) {
            int e = s_idx[w];
            g_lrank[blockIdx.x * 8 + w] = cnt[e];
            cnt[e]++;
        }
#pragma unroll
        for (int e = 0; e < E_NUM; e++) g_bhist[blockIdx.x][e] = cnt[e];
    }
    if (threadIdx.x < E_NUM) atomicAdd(&g_probsum[threadIdx.x], s_prob[threadIdx.x]);
}

__global__ void k_scan() {
    const int PB = NB_GATE / 256;
    int e = blockIdx.x, tid = threadIdx.x;
    int v[PB]; int s = 0;
#pragma unroll
    for (int i = 0; i < PB; i++) { v[i] = g_bhist[tid * PB + i][e]; s += v[i]; }
    __shared__ int sh[256];
    sh[tid] = s; __syncthreads();
    for (int o = 1; o < 256; o <<= 1) {
        int q = (tid >= o) ? sh[tid - o] : 0;
        __syncthreads(); sh[tid] += q; __syncthreads();
    }
    int off = sh[tid] - s;
#pragma unroll
    for (int i = 0; i < PB; i++) { g_boff[tid * PB + i][e] = off; off += v[i]; }
    if (tid == 255) g_count[e] = sh[255];
}

__device__ __forceinline__ void split2(float a, float b, bf16* hi, bf16* lo) {
    bf16 ha = __float2bfloat16(a), hb = __float2bfloat16(b);
    *(__nv_bfloat162*)hi = __halves2bfloat162(ha, hb);
    *(__nv_bfloat162*)lo = __halves2bfloat162(
        __float2bfloat16(a - __bfloat162float(ha)),
        __float2bfloat16(b - __bfloat162float(hb)));
}

__global__ void k_dispatch(const float* __restrict__ x) {
    int t = blockIdx.x;
    int e = g_idx[t];
    int pos = g_boff[t >> 3][e] + g_lrank[t];
    if (pos < CAP) {
        if (threadIdx.x == 0) g_pos[t] = pos;
        float4 v = ((const float4*)(x + (size_t)t * D_DIM))[threadIdx.x];
        size_t b = ((size_t)e * CAP + pos) * D_DIM + threadIdx.x * 4;
        split2(v.x, v.y, g_disp_hi + b, g_disp_lo + b);
        split2(v.z, v.w, g_disp_hi + b + 2, g_disp_lo + b + 2);
    } else if (threadIdx.x == 0) g_pos[t] = -1;
}

__global__ void k_pad() {
    int e = blockIdx.x;
    int c = g_count[e]; if (c > CAP) c = CAP;
    int r1 = (c + 127) & ~127; if (r1 > CAP) r1 = CAP;
    for (int r = c; r < r1; r++) {
        size_t b = ((size_t)e * CAP + r) * D_DIM + threadIdx.x * 4;
        *(float2*)(g_disp_hi + b) = make_float2(0.f, 0.f);
        *(float2*)(g_disp_lo + b) = make_float2(0.f, 0.f);
    }
}

// transpose+split: in [E,R,C] fp32 -> out [E,Cpad,R] bf16 hi/lo
__global__ void k_wsplit(const float* __restrict__ in, bf16* __restrict__ ohi,
                         bf16* __restrict__ olo, int R, int C, int Cpad) {
    __shared__ float s[32][33];
    int e = blockIdx.z;
    const float* ip = in + (size_t)e * R * C;
    size_t ob = (size_t)e * Cpad * R;
    int c0 = blockIdx.x * 32, r0 = blockIdx.y * 32;
    int tx = threadIdx.x, ty = threadIdx.y;
#pragma unroll
    for (int k = 0; k < 4; k++) {
        int r = r0 + ty + 8 * k, c = c0 + tx;
        s[ty + 8 * k][tx] = (c < C) ? ip[(size_t)r * C + c] : 0.f;
    }
    __syncthreads();
#pragma unroll
    for (int k = 0; k < 4; k++) {
        int cc = ty + 8 * k;
        float v = s[tx][cc];
        bf16 h = __float2bfloat16(v);
        size_t o = ob + (size_t)(c0 + cc) * R + r0 + tx;
        ohi[o] = h;
        olo[o] = __float2bfloat16(v - __bfloat162float(h));
    }
}

__global__ void k_combine() {
    int t = blockIdx.x;
    int pos = g_pos[t];
    size_t b = (size_t)t * D_DIM + threadIdx.x * 4;
    if (pos >= 0) {
        int e = g_idx[t];
        float g = g_gate[t];
        float4 v = ((const float4*)(g_oute + ((size_t)e * CAP + pos) * D_DIM))[threadIdx.x];
        split2(v.x * g, v.y * g, g_y_hi + b, g_y_lo + b);
        split2(v.z * g, v.w * g, g_y_hi + b + 2, g_y_lo + b + 2);
    } else {
        *(float2*)(g_y_hi + b) = make_float2(0.f, 0.f);
        *(float2*)(g_y_lo + b) = make_float2(0.f, 0.f);
    }
}

__global__ void k_loss(float* out, int out_size) {
    if (out_size <= N_TOK * NC_DIM) return;
    if (threadIdx.x == 0 && blockIdx.x == 0) {
        float s = 0.f;
        for (int e = 0; e < E_NUM; e++)
            s += ((float)g_count[e] / (float)N_TOK) * (g_probsum[e] / (float)N_TOK);
        out[(size_t)N_TOK * NC_DIM] = s * (float)E_NUM;
    }
}

// ---------------- mma.sync bf16 GEMM: CTA 128x256, BK=64, 2-stage ----------
// A [M,K] row-major bf16 (hi,lo), B [N,K] row-major bf16 (hi,lo)
// C = Ahi*Bhi^T + Ahi*Blo^T + Alo*Bhi^T (fp32 accum)
// warp tile 64x64 (8 warps, 2x4)
#define STG_B 98304
#define OFF_ALO 16384
#define OFF_BHI 32768
#define OFF_BLO 65536
#define GEMM_SMEM (2*STG_B + 128)

__device__ __forceinline__ float gelu_tanh(float v) {
    float u = 0.7978845608028654f * (v + 0.044715f * v * v * v);
    return 0.5f * v * (1.f + tanhf(u));
}
__device__ __forceinline__ uint32_t swz(int row, int c) {
    return (uint32_t)(row * 128 + ((c ^ (row & 7)) << 4));
}

template <int MODE>
__global__ void __launch_bounds__(256, 1) k_mgemm(
    const bf16* __restrict__ Ahi, const bf16* __restrict__ Alo, size_t sAe,
    const bf16* __restrict__ Bhi, const bf16* __restrict__ Blo, size_t sBe,
    const float* __restrict__ bias, int sBiasE,
    void* __restrict__ out0, void* __restrict__ out1, size_t sCe,
    int K, int ldc, int colmax)
{
    int e = blockIdx.z;
    int m0 = blockIdx.y * 128, n0 = blockIdx.x * 256;
    if (MODE < 2) {
        int c = g_count[e]; if (c > CAP) c = CAP;
        if (m0 >= c) return;
    }
    Ahi += (size_t)e * sAe; Alo += (size_t)e * sAe;
    Bhi += (size_t)e * sBe; Blo += (size_t)e * sBe;
    bias += (size_t)e * sBiasE;

    extern __shared__ char smem_raw[];
    uint32_t base = (smem_u32(smem_raw) + 127) & ~127u;

    int tid = threadIdx.x, lane = tid & 31, wid = tid >> 5;
    int wr = wid >> 2, wc = wid & 3;   // warp 64x64 tile at (wr*64, wc*64)

    float acc[4][8][4];
#pragma unroll
    for (int i = 0; i < 4; i++)
#pragma unroll
        for (int j = 0; j < 8; j++)
#pragma unroll
            for (int q = 0; q < 4; q++) acc[i][j][q] = 0.f;

    int nch = K >> 6;

    auto load_chunk = [&](int s, int c) {
        uint32_t stg = base + s * STG_B;
        int k0 = c << 6;
        // A: 128 rows x 8 16B-cols, hi+lo
#pragma unroll
        for (int it = 0; it < 4; it++) {
            int i = tid + it * 256;
            int row = i >> 3, cc = i & 7;
            uint32_t o = swz(row, cc);
            size_t gi = (size_t)(m0 + row) * K + k0 + cc * 8;
            cpa(stg + o, Ahi + gi);
            cpa(stg + OFF_ALO + o, Alo + gi);
        }
        // B: 256 rows x 8 16B-cols, hi+lo
#pragma unroll
        for (int it = 0; it < 8; it++) {
            int i = tid + it * 256;
            int row = i >> 3, cc = i & 7;
            uint32_t o = swz(row, cc);
            size_t gi = (size_t)(n0 + row) * K + k0 + cc * 8;
            cpa(stg + OFF_BHI + o, Bhi + gi);
            cpa(stg + OFF_BLO + o, Blo + gi);
        }
    };

    load_chunk(0, 0); cpa_commit();
    if (nch > 1) { load_chunk(1, 1); cpa_commit(); }

    for (int c = 0; c < nch; c++) {
        int s = c & 1;
        uint32_t stg = base + s * STG_B;
        cpa_wait<1>();
        __syncthreads();

#pragma unroll
        for (int ks = 0; ks < 4; ks++) {
            uint32_t ah[4][4], al[4][4];
            int ar = wr * 64 + (lane & 15);
            int ac = ks * 2 + (lane >> 4);
#pragma unroll
            for (int i = 0; i < 4; i++) {
                uint32_t adr = stg + swz(ar + i * 16, ac);
                ldsm4(ah[i], adr);
                ldsm4(al[i], adr + OFF_ALO);
            }
            int br = wc * 64 + (lane & 7);
            int bc = ks * 2 + ((lane >> 3) & 1);
#pragma unroll
            for (int j = 0; j < 8; j++) {
                uint32_t bh[2], bl[2];
                uint32_t adr = stg + OFF_BHI + swz(br + j * 8, bc);
                ldsm2(bh, adr);
                ldsm2(bl, adr + 32768);
#pragma unroll
                for (int i = 0; i < 4; i++) {
                    mma_bf16(acc[i][j], ah[i], bh);
                    mma_bf16(acc[i][j], ah[i], bl);
                    mma_bf16(acc[i][j], al[i], bh);
                }
            }
        }
        __syncthreads();
        if (c + 2 < nch) { load_chunk(s, c + 2); cpa_commit(); }
    }

    // epilogue
    int rb = m0 + wr * 64, cb = n0 + wc * 64;
#pragma unroll
    for (int i = 0; i < 4; i++)
#pragma unroll
        for (int j = 0; j < 8; j++) {
            int r0 = rb + i * 16 + (lane >> 2);
            int c0 = cb + j * 8 + (lane & 3) * 2;
            float bx = bias[c0], by = bias[c0 + 1];
#pragma unroll
            for (int h = 0; h < 2; h++) {
                int row = r0 + h * 8;
                float v0 = acc[i][j][h * 2 + 0] + bx;
                float v1 = acc[i][j][h * 2 + 1] + by;
                size_t o = (size_t)e * sCe + (size_t)row * ldc + c0;
                if (MODE == 0) {
                    v0 = gelu_tanh(v0); v1 = gelu_tanh(v1);
                    split2(v0, v1, (bf16*)out0 + o, (bf16*)out1 + o);
                } else if (MODE == 1) {
                    *(float2*)((float*)out0 + o) = make_float2(v0, v1);
                } else {
                    size_t oo = (size_t)row * ldc + c0;
                    if (c0 < colmax)     ((float*)out0)[oo] = v0;
                    if (c0 + 1 < colmax) ((float*)out0)[oo + 1] = v1;
                }
            }
        }
}

// ---------------- launch ----------------
extern "C" void kernel_launch(void* const* d_in, const int* in_sizes, int n_in,
                              void* d_out, int out_size) {
    const float* x  = (const float*)d_in[0];
    const float* Wg = (const float*)d_in[1];
    const float* W1 = (const float*)d_in[2];
    const float* b1 = (const float*)d_in[3];
    const float* W2 = (const float*)d_in[4];
    const float* b2 = (const float*)d_in[5];
    const float* Wl = (const float*)d_in[6];
    const float* bl = (const float*)d_in[7];
    float* out = (float*)d_out;

    static int smem_set = 0;
    if (!smem_set) {
        cudaFuncSetAttribute(k_mgemm<0>, cudaFuncAttributeMaxDynamicSharedMemorySize, GEMM_SMEM);
        cudaFuncSetAttribute(k_mgemm<1>, cudaFuncAttributeMaxDynamicSharedMemorySize, GEMM_SMEM);
        cudaFuncSetAttribute(k_mgemm<2>, cudaFuncAttributeMaxDynamicSharedMemorySize, GEMM_SMEM);
        smem_set = 1;
    }

    bf16 *w1h, *w1l, *w2h, *w2l, *wlh, *wll, *dh, *dl, *hh, *hl, *yh, *yl;
    float* oute;
    cudaGetSymbolAddress((void**)&w1h, g_w1t_hi); cudaGetSymbolAddress((void**)&w1l, g_w1t_lo);
    cudaGetSymbolAddress((void**)&w2h, g_w2t_hi); cudaGetSymbolAddress((void**)&w2l, g_w2t_lo);
    cudaGetSymbolAddress((void**)&wlh, g_wlt_hi); cudaGetSymbolAddress((void**)&wll, g_wlt_lo);
    cudaGetSymbolAddress((void**)&dh, g_disp_hi); cudaGetSymbolAddress((void**)&dl, g_disp_lo);
    cudaGetSymbolAddress((void**)&hh, g_h_hi);    cudaGetSymbolAddress((void**)&hl, g_h_lo);
    cudaGetSymbolAddress((void**)&yh, g_y_hi);    cudaGetSymbolAddress((void**)&yl, g_y_lo);
    cudaGetSymbolAddress((void**)&oute, g_oute);

    k_init<<<1, 32>>>();
    k_gate<<<NB_GATE, 256>>>(x, Wg);
    k_scan<<<E_NUM, 256>>>();
    k_dispatch<<<N_TOK, 256>>>(x);
    k_pad<<<E_NUM, 256>>>();

    dim3 tb(32, 8);
    k_wsplit<<<dim3(H_DIM/32, D_DIM/32, E_NUM), tb>>>(W1, w1h, w1l, D_DIM, H_DIM, H_DIM);
    k_wsplit<<<dim3(D_DIM/32, H_DIM/32, E_NUM), tb>>>(W2, w2h, w2l, H_DIM, D_DIM, D_DIM);
    k_wsplit<<<dim3(1024/32, D_DIM/32, 1), tb>>>(Wl, wlh, wll, D_DIM, NC_DIM, 1024);

    // FFN1: [CAP,1024] x [4096,1024]^T -> h [CAP,4096] bf16 hi/lo, gelu
    k_mgemm<0><<<dim3(H_DIM/256, CAP/128, E_NUM), 256, GEMM_SMEM>>>(
        dh, dl, (size_t)CAP*D_DIM, w1h, w1l, (size_t)H_DIM*D_DIM,
        b1, H_DIM, hh, hl, (size_t)CAP*H_DIM, D_DIM, H_DIM, H_DIM);
    // FFN2: [CAP,4096] x [1024,4096]^T -> oute [CAP,1024] f32
    k_mgemm<1><<<dim3(D_DIM/256, CAP/128, E_NUM), 256, GEMM_SMEM>>>(
        hh, hl, (size_t)CAP*H_DIM, w2h, w2l, (size_t)D_DIM*H_DIM,
        b2, D_DIM, oute, nullptr, (size_t)CAP*D_DIM, H_DIM, D_DIM, D_DIM);

    k_combine<<<N_TOK, 256>>>();

    // classifier: [16384,1024] x [1024(pad),1024]^T -> out [16384,1000]
    k_mgemm<2><<<dim3(1024/256, N_TOK/128, 1), 256, GEMM_SMEM>>>(
        yh, yl, 0, wlh, wll, 0,
        bl, 0, out, nullptr, 0, D_DIM, NC_DIM, NC_DIM);

    k_loss<<<1, 32>>>(out, out_size);
}

// round 6
// speedup vs baseline: 2.7360x; 1.0328x over previous
#include <cuda_runtime.h>
#include <cuda_bf16.h>
#include <math.h>
#include <stdint.h>

#define N_TOK 16384
#define D_DIM 1024
#define E_NUM 16
#define H_DIM 4096
#define NC_DIM 1000
#define CAP 2048
#define NB_GATE (N_TOK/8)

typedef __nv_bfloat16 bf16;

// ---------------- device scratch ----------------
__device__ __align__(16) bf16 g_disp_hi[(size_t)E_NUM*CAP*D_DIM];
__device__ __align__(16) bf16 g_disp_lo[(size_t)E_NUM*CAP*D_DIM];
__device__ __align__(16) bf16 g_h_hi[(size_t)E_NUM*CAP*H_DIM];
__device__ __align__(16) bf16 g_h_lo[(size_t)E_NUM*CAP*H_DIM];
__device__ __align__(16) float g_oute[(size_t)E_NUM*CAP*D_DIM];
__device__ __align__(16) bf16 g_y_hi[(size_t)N_TOK*D_DIM];
__device__ __align__(16) bf16 g_y_lo[(size_t)N_TOK*D_DIM];
__device__ __align__(16) bf16 g_w1t_hi[(size_t)E_NUM*H_DIM*D_DIM];
__device__ __align__(16) bf16 g_w1t_lo[(size_t)E_NUM*H_DIM*D_DIM];
__device__ __align__(16) bf16 g_w2t_hi[(size_t)E_NUM*D_DIM*H_DIM];
__device__ __align__(16) bf16 g_w2t_lo[(size_t)E_NUM*D_DIM*H_DIM];
__device__ __align__(16) bf16 g_wlt_hi[(size_t)1024*D_DIM];
__device__ __align__(16) bf16 g_wlt_lo[(size_t)1024*D_DIM];
__device__ int   g_idx[N_TOK];
__device__ float g_gate[N_TOK];
__device__ int   g_lrank[N_TOK];
__device__ int   g_bhist[NB_GATE][E_NUM];
__device__ float g_bprob[NB_GATE][E_NUM];
__device__ int   g_boff[NB_GATE][E_NUM];
__device__ int   g_count[E_NUM];
__device__ float g_probsum[E_NUM];
__device__ int   g_pos[N_TOK];

// ---------------- PTX helpers ----------------
__device__ __forceinline__ uint32_t smem_u32(const void* p) {
    return (uint32_t)__cvta_generic_to_shared(p);
}
__device__ __forceinline__ void cpa(uint32_t dst, const void* src) {
    asm volatile("cp.async.cg.shared.global [%0], [%1], 16;" :: "r"(dst), "l"(src) : "memory");
}
__device__ __forceinline__ void cpa_commit() { asm volatile("cp.async.commit_group;" ::: "memory"); }
template<int N> __device__ __forceinline__ void cpa_wait() {
    asm volatile("cp.async.wait_group %0;" :: "n"(N) : "memory");
}
__device__ __forceinline__ void ldsm4(uint32_t* r, uint32_t a) {
    asm volatile("ldmatrix.sync.aligned.m8n8.x4.shared.b16 {%0,%1,%2,%3}, [%4];"
                 : "=r"(r[0]), "=r"(r[1]), "=r"(r[2]), "=r"(r[3]) : "r"(a));
}
__device__ __forceinline__ void mma_bf16(float* d, const uint32_t* a, const uint32_t* b) {
    asm volatile(
        "mma.sync.aligned.m16n8k16.row.col.f32.bf16.bf16.f32 "
        "{%0,%1,%2,%3}, {%4,%5,%6,%7}, {%8,%9}, {%0,%1,%2,%3};"
        : "+f"(d[0]), "+f"(d[1]), "+f"(d[2]), "+f"(d[3])
        : "r"(a[0]), "r"(a[1]), "r"(a[2]), "r"(a[3]), "r"(b[0]), "r"(b[1]));
}

// ---------------- gating ----------------
__global__ void k_gate(const float* __restrict__ x, const float* __restrict__ Wg) {
    int warp = threadIdx.x >> 5, lane = threadIdx.x & 31;
    int t = blockIdx.x * 8 + warp;
    __shared__ float s_prob[E_NUM];
    __shared__ int s_idx[8];
    if (threadIdx.x < E_NUM) s_prob[threadIdx.x] = 0.f;
    __syncthreads();
    float acc[E_NUM];
#pragma unroll
    for (int e = 0; e < E_NUM; e++) acc[e] = 0.f;
    const float* xr = x + (size_t)t * D_DIM;
    for (int j = 0; j < D_DIM / 32; j++) {
        float xv = xr[lane + 32 * j];
        const float* wr = Wg + (size_t)(lane + 32 * j) * E_NUM;
#pragma unroll
        for (int e = 0; e < E_NUM; e++) acc[e] = fmaf(xv, __ldg(wr + e), acc[e]);
    }
#pragma unroll
    for (int e = 0; e < E_NUM; e++)
#pragma unroll
        for (int o = 16; o > 0; o >>= 1) acc[e] += __shfl_xor_sync(0xffffffffu, acc[e], o);
    if (lane == 0) {
        float m = acc[0]; int ai = 0;
#pragma unroll
        for (int e = 1; e < E_NUM; e++) if (acc[e] > m) { m = acc[e]; ai = e; }
        float p[E_NUM]; float s = 0.f;
#pragma unroll
        for (int e = 0; e < E_NUM; e++) { p[e] = expf(acc[e] - m); s += p[e]; }
        float inv = 1.f / s;
#pragma unroll
        for (int e = 0; e < E_NUM; e++) atomicAdd(&s_prob[e], p[e] * inv);
        g_idx[t] = ai; g_gate[t] = p[ai] * inv; s_idx[warp] = ai;
    }
    __syncthreads();
    if (threadIdx.x == 0) {
        int cnt[E_NUM];
#pragma unroll
        for (int e = 0; e < E_NUM; e++) cnt[e] = 0;
#pragma unroll
        for (int w = 0; w < 8; w++) {
            int e = s_idx[w];
            g_lrank[blockIdx.x * 8 + w] = cnt[e];
            cnt[e]++;
        }
#pragma unroll
        for (int e = 0; e < E_NUM; e++) g_bhist[blockIdx.x][e] = cnt[e];
    }
    if (threadIdx.x < E_NUM) g_bprob[blockIdx.x][threadIdx.x] = s_prob[threadIdx.x];
}

// ---------------- scan + probsum reduce + pad ----------------
__global__ void k_scan() {
    const int PB = NB_GATE / 256;
    int e = blockIdx.x, tid = threadIdx.x;
    int v[PB]; int s = 0;
    float ps = 0.f;
#pragma unroll
    for (int i = 0; i < PB; i++) {
        v[i] = g_bhist[tid * PB + i][e];
        s += v[i];
        ps += g_bprob[tid * PB + i][e];
    }
    __shared__ int sh[256];
    __shared__ float sp[256];
    sh[tid] = s; sp[tid] = ps;
    __syncthreads();
    for (int o = 1; o < 256; o <<= 1) {
        int q = (tid >= o) ? sh[tid - o] : 0;
        __syncthreads(); sh[tid] += q; __syncthreads();
    }
    int off = sh[tid] - s;
#pragma unroll
    for (int i = 0; i < PB; i++) { g_boff[tid * PB + i][e] = off; off += v[i]; }
    for (int o = 128; o > 0; o >>= 1) {
        if (tid < o) sp[tid] += sp[tid + o];
        __syncthreads();
    }
    if (tid == 0) { g_count[e] = sh[255]; g_probsum[e] = sp[0]; }
    __syncthreads();
    // pad dispatched rows [count, round128(count)) with zeros
    int c = sh[255]; if (c > CAP) c = CAP;
    int r1 = (c + 127) & ~127; if (r1 > CAP) r1 = CAP;
    for (int r = c; r < r1; r++) {
        size_t b = ((size_t)e * CAP + r) * D_DIM + tid * 4;
        *(float2*)(g_disp_hi + b) = make_float2(0.f, 0.f);
        *(float2*)(g_disp_lo + b) = make_float2(0.f, 0.f);
    }
}

__device__ __forceinline__ void split2(float a, float b, bf16* hi, bf16* lo) {
    bf16 ha = __float2bfloat16(a), hb = __float2bfloat16(b);
    *(__nv_bfloat162*)hi = __halves2bfloat162(ha, hb);
    *(__nv_bfloat162*)lo = __halves2bfloat162(
        __float2bfloat16(a - __bfloat162float(ha)),
        __float2bfloat16(b - __bfloat162float(hb)));
}

// wsplit body: in [E,R,C] fp32 -> out [E,Cpad,R] bf16 hi/lo
__device__ __forceinline__ void wsplit_body(
    const float* __restrict__ in, bf16* __restrict__ ohi, bf16* __restrict__ olo,
    int R, int C, int Cpad, int bx, int by, int bz, int tid)
{
    __shared__ float s[32][33];
    const float* ip = in + (size_t)bz * R * C;
    size_t ob = (size_t)bz * Cpad * R;
    int c0 = bx * 32, r0 = by * 32;
    int tx = tid & 31, ty = tid >> 5;
#pragma unroll
    for (int k = 0; k < 4; k++) {
        int r = r0 + ty + 8 * k, c = c0 + tx;
        s[ty + 8 * k][tx] = (c < C) ? ip[(size_t)r * C + c] : 0.f;
    }
    __syncthreads();
#pragma unroll
    for (int k = 0; k < 4; k++) {
        int cc = ty + 8 * k;
        float v = s[tx][cc];
        bf16 h = __float2bfloat16(v);
        size_t o = ob + (size_t)(c0 + cc) * R + r0 + tx;
        ohi[o] = h;
        olo[o] = __float2bfloat16(v - __bfloat162float(h));
    }
}

// fused: dispatch (16384) + wsplit W1 (65536) + wsplit W2 (65536) + wsplit Wl (1024)
#define BIG_W1 16384
#define BIG_W2 (16384 + 65536)
#define BIG_WL (16384 + 2*65536)
#define BIG_TOT (16384 + 2*65536 + 1024)

__global__ void k_big(const float* __restrict__ x, const float* __restrict__ W1,
                      const float* __restrict__ W2, const float* __restrict__ Wl) {
    int b = blockIdx.x, tid = threadIdx.x;
    if (b < BIG_W1) {
        int t = b;
        int e = g_idx[t];
        int pos = g_boff[t >> 3][e] + g_lrank[t];
        if (pos < CAP) {
            if (tid == 0) g_pos[t] = pos;
            float4 v = ((const float4*)(x + (size_t)t * D_DIM))[tid];
            size_t o = ((size_t)e * CAP + pos) * D_DIM + tid * 4;
            split2(v.x, v.y, g_disp_hi + o, g_disp_lo + o);
            split2(v.z, v.w, g_disp_hi + o + 2, g_disp_lo + o + 2);
        } else if (tid == 0) g_pos[t] = -1;
    } else if (b < BIG_W2) {
        int i = b - BIG_W1;                      // W1: R=D(1024) C=H(4096) Cpad=H
        int bx = i % 128, by = (i / 128) % 32, bz = i / (128 * 32);
        wsplit_body(W1, g_w1t_hi, g_w1t_lo, D_DIM, H_DIM, H_DIM, bx, by, bz, tid);
    } else if (b < BIG_WL) {
        int i = b - BIG_W2;                      // W2: R=H(4096) C=D(1024) Cpad=D
        int bx = i % 32, by = (i / 32) % 128, bz = i / (32 * 128);
        wsplit_body(W2, g_w2t_hi, g_w2t_lo, H_DIM, D_DIM, D_DIM, bx, by, bz, tid);
    } else {
        int i = b - BIG_WL;                      // Wl: R=D(1024) C=NC(1000) Cpad=1024
        int bx = i % 32, by = i / 32;
        wsplit_body(Wl, g_wlt_hi, g_wlt_lo, D_DIM, NC_DIM, 1024, bx, by, 0, tid);
    }
}

__global__ void k_combine() {
    int t = blockIdx.x;
    int pos = g_pos[t];
    size_t b = (size_t)t * D_DIM + threadIdx.x * 4;
    if (pos >= 0) {
        int e = g_idx[t];
        float g = g_gate[t];
        float4 v = ((const float4*)(g_oute + ((size_t)e * CAP + pos) * D_DIM))[threadIdx.x];
        split2(v.x * g, v.y * g, g_y_hi + b, g_y_lo + b);
        split2(v.z * g, v.w * g, g_y_hi + b + 2, g_y_lo + b + 2);
    } else {
        *(float2*)(g_y_hi + b) = make_float2(0.f, 0.f);
        *(float2*)(g_y_lo + b) = make_float2(0.f, 0.f);
    }
}

__global__ void k_loss(float* out, int out_size) {
    if (out_size <= N_TOK * NC_DIM) return;
    if (threadIdx.x == 0 && blockIdx.x == 0) {
        float s = 0.f;
        for (int e = 0; e < E_NUM; e++)
            s += ((float)g_count[e] / (float)N_TOK) * (g_probsum[e] / (float)N_TOK);
        out[(size_t)N_TOK * NC_DIM] = s * (float)E_NUM;
    }
}

// ---------------- mma.sync bf16 GEMM: CTA 128x256, BK=64, 2-stage ----------
#define STG_B 98304
#define OFF_ALO 16384
#define OFF_BHI 32768
#define OFF_BLO 65536
#define GEMM_SMEM (2*STG_B + 128)

__device__ __forceinline__ float gelu_tanh(float v) {
    float u = 0.7978845608028654f * (v + 0.044715f * v * v * v);
    return 0.5f * v * (1.f + tanhf(u));
}
__device__ __forceinline__ uint32_t swz(int row, int c) {
    return (uint32_t)(row * 128 + ((c ^ (row & 7)) << 4));
}

template <int MODE>
__global__ void __launch_bounds__(256, 1) k_mgemm(
    const bf16* __restrict__ Ahi, const bf16* __restrict__ Alo, size_t sAe,
    const bf16* __restrict__ Bhi, const bf16* __restrict__ Blo, size_t sBe,
    const float* __restrict__ bias, int sBiasE,
    void* __restrict__ out0, void* __restrict__ out1, size_t sCe,
    int K, int ldc, int colmax)
{
    int e = blockIdx.z;
    int m0 = blockIdx.y * 128, n0 = blockIdx.x * 256;
    if (MODE < 2) {
        int c = g_count[e]; if (c > CAP) c = CAP;
        if (m0 >= c) return;
    }
    Ahi += (size_t)e * sAe; Alo += (size_t)e * sAe;
    Bhi += (size_t)e * sBe; Blo += (size_t)e * sBe;
    bias += (size_t)e * sBiasE;

    extern __shared__ char smem_raw[];
    uint32_t base = (smem_u32(smem_raw) + 127) & ~127u;

    int tid = threadIdx.x, lane = tid & 31, wid = tid >> 5;
    int wr = wid >> 2, wc = wid & 3;

    float acc[4][8][4];
#pragma unroll
    for (int i = 0; i < 4; i++)
#pragma unroll
        for (int j = 0; j < 8; j++)
#pragma unroll
            for (int q = 0; q < 4; q++) acc[i][j][q] = 0.f;

    int nch = K >> 6;

    auto load_chunk = [&](int s, int c) {
        uint32_t stg = base + s * STG_B;
        int k0 = c << 6;
#pragma unroll
        for (int it = 0; it < 4; it++) {
            int i = tid + it * 256;
            int row = i >> 3, cc = i & 7;
            uint32_t o = swz(row, cc);
            size_t gi = (size_t)(m0 + row) * K + k0 + cc * 8;
            cpa(stg + o, Ahi + gi);
            cpa(stg + OFF_ALO + o, Alo + gi);
        }
#pragma unroll
        for (int it = 0; it < 8; it++) {
            int i = tid + it * 256;
            int row = i >> 3, cc = i & 7;
            uint32_t o = swz(row, cc);
            size_t gi = (size_t)(n0 + row) * K + k0 + cc * 8;
            cpa(stg + OFF_BHI + o, Bhi + gi);
            cpa(stg + OFF_BLO + o, Blo + gi);
        }
    };

    load_chunk(0, 0); cpa_commit();
    if (nch > 1) { load_chunk(1, 1); cpa_commit(); }

    for (int c = 0; c < nch; c++) {
        int s = c & 1;
        uint32_t stg = base + s * STG_B;
        cpa_wait<1>();
        __syncthreads();

#pragma unroll
        for (int ks = 0; ks < 4; ks++) {
            uint32_t ah[4][4], al[4][4];
            int ar = wr * 64 + (lane & 15);
            int ac = ks * 2 + (lane >> 4);
#pragma unroll
            for (int i = 0; i < 4; i++) {
                uint32_t adr = stg + swz(ar + i * 16, ac);
                ldsm4(ah[i], adr);
                ldsm4(al[i], adr + OFF_ALO);
            }
            // B via ldsm4 over j-pairs: lanes 0-7 (j even, k0), 8-15 (j even, k1),
            // 16-23 (j odd, k0), 24-31 (j odd, k1)
            int jj = (lane >> 4);
            int brr = wc * 64 + (lane & 7);
            int bcc = ks * 2 + ((lane >> 3) & 1);
#pragma unroll
            for (int j2 = 0; j2 < 4; j2++) {
                uint32_t bh[4], bl[4];
                uint32_t adr = stg + OFF_BHI + swz(brr + (j2 * 2 + jj) * 8, bcc);
                ldsm4(bh, adr);
                ldsm4(bl, adr + 32768);
#pragma unroll
                for (int i = 0; i < 4; i++) {
                    mma_bf16(acc[i][j2 * 2 + 0], ah[i], bh + 0);
                    mma_bf16(acc[i][j2 * 2 + 0], ah[i], bl + 0);
                    mma_bf16(acc[i][j2 * 2 + 0], al[i], bh + 0);
                    mma_bf16(acc[i][j2 * 2 + 1], ah[i], bh + 2);
                    mma_bf16(acc[i][j2 * 2 + 1], ah[i], bl + 2);
                    mma_bf16(acc[i][j2 * 2 + 1], al[i], bh + 2);
                }
            }
        }
        __syncthreads();
        if (c + 2 < nch) { load_chunk(s, c + 2); cpa_commit(); }
    }

    int rb = m0 + wr * 64, cb = n0 + wc * 64;
#pragma unroll
    for (int i = 0; i < 4; i++)
#pragma unroll
        for (int j = 0; j < 8; j++) {
            int r0 = rb + i * 16 + (lane >> 2);
            int c0 = cb + j * 8 + (lane & 3) * 2;
            float bx = bias[c0], by = bias[c0 + 1];
#pragma unroll
            for (int h = 0; h < 2; h++) {
                int row = r0 + h * 8;
                float v0 = acc[i][j][h * 2 + 0] + bx;
                float v1 = acc[i][j][h * 2 + 1] + by;
                size_t o = (size_t)e * sCe + (size_t)row * ldc + c0;
                if (MODE == 0) {
                    v0 = gelu_tanh(v0); v1 = gelu_tanh(v1);
                    split2(v0, v1, (bf16*)out0 + o, (bf16*)out1 + o);
                } else if (MODE == 1) {
                    *(float2*)((float*)out0 + o) = make_float2(v0, v1);
                } else {
                    size_t oo = (size_t)row * ldc + c0;
                    if (c0 < colmax)     ((float*)out0)[oo] = v0;
                    if (c0 + 1 < colmax) ((float*)out0)[oo + 1] = v1;
                }
            }
        }
}

// ---------------- launch ----------------
extern "C" void kernel_launch(void* const* d_in, const int* in_sizes, int n_in,
                              void* d_out, int out_size) {
    const float* x  = (const float*)d_in[0];
    const float* Wg = (const float*)d_in[1];
    const float* W1 = (const float*)d_in[2];
    const float* b1 = (const float*)d_in[3];
    const float* W2 = (const float*)d_in[4];
    const float* b2 = (const float*)d_in[5];
    const float* Wl = (const float*)d_in[6];
    const float* bl = (const float*)d_in[7];
    float* out = (float*)d_out;

    static int smem_set = 0;
    if (!smem_set) {
        cudaFuncSetAttribute(k_mgemm<0>, cudaFuncAttributeMaxDynamicSharedMemorySize, GEMM_SMEM);
        cudaFuncSetAttribute(k_mgemm<1>, cudaFuncAttributeMaxDynamicSharedMemorySize, GEMM_SMEM);
        cudaFuncSetAttribute(k_mgemm<2>, cudaFuncAttributeMaxDynamicSharedMemorySize, GEMM_SMEM);
        smem_set = 1;
    }

    bf16 *w1h, *w1l, *w2h, *w2l, *wlh, *wll, *dh, *dl, *hh, *hl, *yh, *yl;
    float* oute;
    cudaGetSymbolAddress((void**)&w1h, g_w1t_hi); cudaGetSymbolAddress((void**)&w1l, g_w1t_lo);
    cudaGetSymbolAddress((void**)&w2h, g_w2t_hi); cudaGetSymbolAddress((void**)&w2l, g_w2t_lo);
    cudaGetSymbolAddress((void**)&wlh, g_wlt_hi); cudaGetSymbolAddress((void**)&wll, g_wlt_lo);
    cudaGetSymbolAddress((void**)&dh, g_disp_hi); cudaGetSymbolAddress((void**)&dl, g_disp_lo);
    cudaGetSymbolAddress((void**)&hh, g_h_hi);    cudaGetSymbolAddress((void**)&hl, g_h_lo);
    cudaGetSymbolAddress((void**)&yh, g_y_hi);    cudaGetSymbolAddress((void**)&yl, g_y_lo);
    cudaGetSymbolAddress((void**)&oute, g_oute);

    k_gate<<<NB_GATE, 256>>>(x, Wg);          // launch 1
    k_scan<<<E_NUM, 256>>>();                 // launch 2
    k_big<<<BIG_TOT, 256>>>(x, W1, W2, Wl);   // launch 3

    // launch 4 (ncu target): FFN1 [CAP,1024] x [4096,1024]^T -> h bf16 hi/lo, gelu
    k_mgemm<0><<<dim3(H_DIM/256, CAP/128, E_NUM), 256, GEMM_SMEM>>>(
        dh, dl, (size_t)CAP*D_DIM, w1h, w1l, (size_t)H_DIM*D_DIM,
        b1, H_DIM, hh, hl, (size_t)CAP*H_DIM, D_DIM, H_DIM, H_DIM);
    // FFN2
    k_mgemm<1><<<dim3(D_DIM/256, CAP/128, E_NUM), 256, GEMM_SMEM>>>(
        hh, hl, (size_t)CAP*H_DIM, w2h, w2l, (size_t)D_DIM*H_DIM,
        b2, D_DIM, oute, nullptr, (size_t)CAP*D_DIM, H_DIM, D_DIM, D_DIM);

    k_combine<<<N_TOK, 256>>>();

    // classifier
    k_mgemm<2><<<dim3(1024/256, N_TOK/128, 1), 256, GEMM_SMEM>>>(
        yh, yl, 0, wlh, wll, 0,
        bl, 0, out, nullptr, 0, D_DIM, NC_DIM, NC_DIM);

    k_loss<<<1, 32>>>(out, out_size);
}

// round 7
// speedup vs baseline: 2.7537x; 1.0065x over previous
#include <cuda_runtime.h>
#include <cuda_bf16.h>
#include <math.h>
#include <stdint.h>

#define N_TOK 16384
#define D_DIM 1024
#define E_NUM 16
#define H_DIM 4096
#define NC_DIM 1000
#define CAP 2048
#define NB_GATE (N_TOK/8)

typedef __nv_bfloat16 bf16;

// ---------------- device scratch ----------------
__device__ __align__(16) bf16 g_disp_hi[(size_t)E_NUM*CAP*D_DIM];
__device__ __align__(16) bf16 g_disp_lo[(size_t)E_NUM*CAP*D_DIM];
__device__ __align__(16) bf16 g_h_hi[(size_t)E_NUM*CAP*H_DIM];
__device__ __align__(16) bf16 g_h_lo[(size_t)E_NUM*CAP*H_DIM];
__device__ __align__(16) float g_oute[(size_t)E_NUM*CAP*D_DIM];
__device__ __align__(16) bf16 g_y_hi[(size_t)N_TOK*D_DIM];
__device__ __align__(16) bf16 g_y_lo[(size_t)N_TOK*D_DIM];
__device__ __align__(16) bf16 g_w1t_hi[(size_t)E_NUM*H_DIM*D_DIM];
__device__ __align__(16) bf16 g_w1t_lo[(size_t)E_NUM*H_DIM*D_DIM];
__device__ __align__(16) bf16 g_w2t_hi[(size_t)E_NUM*D_DIM*H_DIM];
__device__ __align__(16) bf16 g_w2t_lo[(size_t)E_NUM*D_DIM*H_DIM];
__device__ __align__(16) bf16 g_wlt_hi[(size_t)1024*D_DIM];
__device__ __align__(16) bf16 g_wlt_lo[(size_t)1024*D_DIM];
__device__ int   g_idx[N_TOK];
__device__ float g_gate[N_TOK];
__device__ int   g_lrank[N_TOK];
__device__ int   g_bhist[NB_GATE][E_NUM];
__device__ float g_bprob[NB_GATE][E_NUM];
__device__ int   g_boff[NB_GATE][E_NUM];
__device__ int   g_count[E_NUM];
__device__ float g_probsum[E_NUM];
__device__ int   g_pos[N_TOK];

// ---------------- PTX helpers ----------------
__device__ __forceinline__ uint32_t smem_u32(const void* p) {
    return (uint32_t)__cvta_generic_to_shared(p);
}
__device__ __forceinline__ void cpa(uint32_t dst, const void* src) {
    asm volatile("cp.async.cg.shared.global [%0], [%1], 16;" :: "r"(dst), "l"(src) : "memory");
}
__device__ __forceinline__ void cpa_commit() { asm volatile("cp.async.commit_group;" ::: "memory"); }
template<int N> __device__ __forceinline__ void cpa_wait() {
    asm volatile("cp.async.wait_group %0;" :: "n"(N) : "memory");
}
__device__ __forceinline__ void ldsm4(uint32_t* r, uint32_t a) {
    asm volatile("ldmatrix.sync.aligned.m8n8.x4.shared.b16 {%0,%1,%2,%3}, [%4];"
                 : "=r"(r[0]), "=r"(r[1]), "=r"(r[2]), "=r"(r[3]) : "r"(a));
}
__device__ __forceinline__ void mma_bf16(float* d, const uint32_t* a, const uint32_t* b) {
    asm volatile(
        "mma.sync.aligned.m16n8k16.row.col.f32.bf16.bf16.f32 "
        "{%0,%1,%2,%3}, {%4,%5,%6,%7}, {%8,%9}, {%0,%1,%2,%3};"
        : "+f"(d[0]), "+f"(d[1]), "+f"(d[2]), "+f"(d[3])
        : "r"(a[0]), "r"(a[1]), "r"(a[2]), "r"(a[3]), "r"(b[0]), "r"(b[1]));
}

// ---------------- gating ----------------
__global__ void k_gate(const float* __restrict__ x, const float* __restrict__ Wg) {
    int warp = threadIdx.x >> 5, lane = threadIdx.x & 31;
    int t = blockIdx.x * 8 + warp;
    __shared__ float s_prob[E_NUM];
    __shared__ int s_idx[8];
    if (threadIdx.x < E_NUM) s_prob[threadIdx.x] = 0.f;
    __syncthreads();
    float acc[E_NUM];
#pragma unroll
    for (int e = 0; e < E_NUM; e++) acc[e] = 0.f;
    const float* xr = x + (size_t)t * D_DIM;
    for (int j = 0; j < D_DIM / 32; j++) {
        float xv = xr[lane + 32 * j];
        const float* wr = Wg + (size_t)(lane + 32 * j) * E_NUM;
#pragma unroll
        for (int e = 0; e < E_NUM; e++) acc[e] = fmaf(xv, __ldg(wr + e), acc[e]);
    }
#pragma unroll
    for (int e = 0; e < E_NUM; e++)
#pragma unroll
        for (int o = 16; o > 0; o >>= 1) acc[e] += __shfl_xor_sync(0xffffffffu, acc[e], o);
    if (lane == 0) {
        float m = acc[0]; int ai = 0;
#pragma unroll
        for (int e = 1; e < E_NUM; e++) if (acc[e] > m) { m = acc[e]; ai = e; }
        float p[E_NUM]; float s = 0.f;
#pragma unroll
        for (int e = 0; e < E_NUM; e++) { p[e] = expf(acc[e] - m); s += p[e]; }
        float inv = 1.f / s;
#pragma unroll
        for (int e = 0; e < E_NUM; e++) atomicAdd(&s_prob[e], p[e] * inv);
        g_idx[t] = ai; g_gate[t] = p[ai] * inv; s_idx[warp] = ai;
    }
    __syncthreads();
    if (threadIdx.x == 0) {
        int cnt[E_NUM];
#pragma unroll
        for (int e = 0; e < E_NUM; e++) cnt[e] = 0;
#pragma unroll
        for (int w = 0; w < 8; w++) {
            int e = s_idx[w];
            g_lrank[blockIdx.x * 8 + w] = cnt[e];
            cnt[e]++;
        }
#pragma unroll
        for (int e = 0; e < E_NUM; e++) g_bhist[blockIdx.x][e] = cnt[e];
    }
    if (threadIdx.x < E_NUM) g_bprob[blockIdx.x][threadIdx.x] = s_prob[threadIdx.x];
}

// ---------------- scan + probsum reduce + pad ----------------
__global__ void k_scan() {
    const int PB = NB_GATE / 256;
    int e = blockIdx.x, tid = threadIdx.x;
    int v[PB]; int s = 0;
    float ps = 0.f;
#pragma unroll
    for (int i = 0; i < PB; i++) {
        v[i] = g_bhist[tid * PB + i][e];
        s += v[i];
        ps += g_bprob[tid * PB + i][e];
    }
    __shared__ int sh[256];
    __shared__ float sp[256];
    sh[tid] = s; sp[tid] = ps;
    __syncthreads();
    for (int o = 1; o < 256; o <<= 1) {
        int q = (tid >= o) ? sh[tid - o] : 0;
        __syncthreads(); sh[tid] += q; __syncthreads();
    }
    int off = sh[tid] - s;
#pragma unroll
    for (int i = 0; i < PB; i++) { g_boff[tid * PB + i][e] = off; off += v[i]; }
    for (int o = 128; o > 0; o >>= 1) {
        if (tid < o) sp[tid] += sp[tid + o];
        __syncthreads();
    }
    if (tid == 0) { g_count[e] = sh[255]; g_probsum[e] = sp[0]; }
    __syncthreads();
    int c = sh[255]; if (c > CAP) c = CAP;
    int r1 = (c + 127) & ~127; if (r1 > CAP) r1 = CAP;
    for (int r = c; r < r1; r++) {
        size_t b = ((size_t)e * CAP + r) * D_DIM + tid * 4;
        *(float2*)(g_disp_hi + b) = make_float2(0.f, 0.f);
        *(float2*)(g_disp_lo + b) = make_float2(0.f, 0.f);
    }
}

__device__ __forceinline__ void split2(float a, float b, bf16* hi, bf16* lo) {
    bf16 ha = __float2bfloat16(a), hb = __float2bfloat16(b);
    *(__nv_bfloat162*)hi = __halves2bfloat162(ha, hb);
    *(__nv_bfloat162*)lo = __halves2bfloat162(
        __float2bfloat16(a - __bfloat162float(ha)),
        __float2bfloat16(b - __bfloat162float(hb)));
}

// wsplit body: in [E,R,C] fp32 -> out [E,Cpad,R] bf16 hi/lo
__device__ __forceinline__ void wsplit_body(
    const float* __restrict__ in, bf16* __restrict__ ohi, bf16* __restrict__ olo,
    int R, int C, int Cpad, int bx, int by, int bz, int tid)
{
    __shared__ float s[32][33];
    const float* ip = in + (size_t)bz * R * C;
    size_t ob = (size_t)bz * Cpad * R;
    int c0 = bx * 32, r0 = by * 32;
    int tx = tid & 31, ty = tid >> 5;
#pragma unroll
    for (int k = 0; k < 4; k++) {
        int r = r0 + ty + 8 * k, c = c0 + tx;
        s[ty + 8 * k][tx] = (c < C) ? ip[(size_t)r * C + c] : 0.f;
    }
    __syncthreads();
#pragma unroll
    for (int k = 0; k < 4; k++) {
        int cc = ty + 8 * k;
        float v = s[tx][cc];
        bf16 h = __float2bfloat16(v);
        size_t o = ob + (size_t)(c0 + cc) * R + r0 + tx;
        ohi[o] = h;
        olo[o] = __float2bfloat16(v - __bfloat162float(h));
    }
}

#define BIG_W1 16384
#define BIG_W2 (16384 + 65536)
#define BIG_WL (16384 + 2*65536)
#define BIG_TOT (16384 + 2*65536 + 1024)

__global__ void k_big(const float* __restrict__ x, const float* __restrict__ W1,
                      const float* __restrict__ W2, const float* __restrict__ Wl) {
    int b = blockIdx.x, tid = threadIdx.x;
    if (b < BIG_W1) {
        int t = b;
        int e = g_idx[t];
        int pos = g_boff[t >> 3][e] + g_lrank[t];
        if (pos < CAP) {
            if (tid == 0) g_pos[t] = pos;
            float4 v = ((const float4*)(x + (size_t)t * D_DIM))[tid];
            size_t o = ((size_t)e * CAP + pos) * D_DIM + tid * 4;
            split2(v.x, v.y, g_disp_hi + o, g_disp_lo + o);
            split2(v.z, v.w, g_disp_hi + o + 2, g_disp_lo + o + 2);
        } else if (tid == 0) g_pos[t] = -1;
    } else if (b < BIG_W2) {
        int i = b - BIG_W1;
        int bx = i % 128, by = (i / 128) % 32, bz = i / (128 * 32);
        wsplit_body(W1, g_w1t_hi, g_w1t_lo, D_DIM, H_DIM, H_DIM, bx, by, bz, tid);
    } else if (b < BIG_WL) {
        int i = b - BIG_W2;
        int bx = i % 32, by = (i / 32) % 128, bz = i / (32 * 128);
        wsplit_body(W2, g_w2t_hi, g_w2t_lo, H_DIM, D_DIM, D_DIM, bx, by, bz, tid);
    } else {
        int i = b - BIG_WL;
        int bx = i % 32, by = i / 32;
        wsplit_body(Wl, g_wlt_hi, g_wlt_lo, D_DIM, NC_DIM, 1024, bx, by, 0, tid);
    }
}

__global__ void k_combine() {
    int t = blockIdx.x;
    int pos = g_pos[t];
    size_t b = (size_t)t * D_DIM + threadIdx.x * 4;
    if (pos >= 0) {
        int e = g_idx[t];
        float g = g_gate[t];
        float4 v = ((const float4*)(g_oute + ((size_t)e * CAP + pos) * D_DIM))[threadIdx.x];
        split2(v.x * g, v.y * g, g_y_hi + b, g_y_lo + b);
        split2(v.z * g, v.w * g, g_y_hi + b + 2, g_y_lo + b + 2);
    } else {
        *(float2*)(g_y_hi + b) = make_float2(0.f, 0.f);
        *(float2*)(g_y_lo + b) = make_float2(0.f, 0.f);
    }
}

__global__ void k_loss(float* out, int out_size) {
    if (out_size <= N_TOK * NC_DIM) return;
    if (threadIdx.x == 0 && blockIdx.x == 0) {
        float s = 0.f;
        for (int e = 0; e < E_NUM; e++)
            s += ((float)g_count[e] / (float)N_TOK) * (g_probsum[e] / (float)N_TOK);
        out[(size_t)N_TOK * NC_DIM] = s * (float)E_NUM;
    }
}

// ---------------- mma.sync bf16 GEMM: CTA 128x256, BK=64, 2-stage ----------
#define STG_B 98304
#define OFF_ALO 16384
#define OFF_BHI 32768
#define OFF_BLO 65536
#define GEMM_SMEM (2*STG_B + 128)

__device__ __forceinline__ float gelu_fast(float v) {
    float u = 0.7978845608028654f * (v + 0.044715f * v * v * v);
    float t;
    asm("tanh.approx.f32 %0, %1;" : "=f"(t) : "f"(u));
    return 0.5f * v * (1.f + t);
}
__device__ __forceinline__ uint32_t swz(int row, int c) {
    return (uint32_t)(row * 128 + ((c ^ (row & 7)) << 4));
}

template <int MODE>
__global__ void __launch_bounds__(256, 1) k_mgemm(
    const bf16* __restrict__ Ahi, const bf16* __restrict__ Alo, size_t sAe,
    const bf16* __restrict__ Bhi, const bf16* __restrict__ Blo, size_t sBe,
    const float* __restrict__ bias, int sBiasE,
    void* __restrict__ out0, void* __restrict__ out1, size_t sCe,
    int K, int ldc, int colmax)
{
    int e = blockIdx.z;
    int m0 = blockIdx.y * 128, n0 = blockIdx.x * 256;
    if (MODE < 2) {
        int c = g_count[e]; if (c > CAP) c = CAP;
        if (m0 >= c) return;
    }
    Ahi += (size_t)e * sAe; Alo += (size_t)e * sAe;
    Bhi += (size_t)e * sBe; Blo += (size_t)e * sBe;
    bias += (size_t)e * sBiasE;

    extern __shared__ char smem_raw[];
    uint32_t base = (smem_u32(smem_raw) + 127) & ~127u;

    int tid = threadIdx.x, lane = tid & 31, wid = tid >> 5;
    int wr = wid >> 2, wc = wid & 3;

    float acc[4][8][4];
#pragma unroll
    for (int i = 0; i < 4; i++)
#pragma unroll
        for (int j = 0; j < 8; j++)
#pragma unroll
            for (int q = 0; q < 4; q++) acc[i][j][q] = 0.f;

    int nch = K >> 6;

    auto load_chunk = [&](int s, int c) {
        uint32_t stg = base + s * STG_B;
        int k0 = c << 6;
#pragma unroll
        for (int it = 0; it < 4; it++) {
            int i = tid + it * 256;
            int row = i >> 3, cc = i & 7;
            uint32_t o = swz(row, cc);
            size_t gi = (size_t)(m0 + row) * K + k0 + cc * 8;
            cpa(stg + o, Ahi + gi);
            cpa(stg + OFF_ALO + o, Alo + gi);
        }
#pragma unroll
        for (int it = 0; it < 8; it++) {
            int i = tid + it * 256;
            int row = i >> 3, cc = i & 7;
            uint32_t o = swz(row, cc);
            size_t gi = (size_t)(n0 + row) * K + k0 + cc * 8;
            cpa(stg + OFF_BHI + o, Bhi + gi);
            cpa(stg + OFF_BLO + o, Blo + gi);
        }
    };

    load_chunk(0, 0); cpa_commit();
    if (nch > 1) { load_chunk(1, 1); cpa_commit(); }

    for (int c = 0; c < nch; c++) {
        int s = c & 1;
        uint32_t stg = base + s * STG_B;
        cpa_wait<1>();
        __syncthreads();

#pragma unroll
        for (int ks = 0; ks < 4; ks++) {
            uint32_t ah[4][4], al[4][4];
            int ar = wr * 64 + (lane & 15);
            int ac = ks * 2 + (lane >> 4);
#pragma unroll
            for (int i = 0; i < 4; i++) {
                uint32_t adr = stg + swz(ar + i * 16, ac);
                ldsm4(ah[i], adr);
                ldsm4(al[i], adr + OFF_ALO);
            }
            int jj = (lane >> 4);
            int brr = wc * 64 + (lane & 7);
            int bcc = ks * 2 + ((lane >> 3) & 1);
#pragma unroll
            for (int j2 = 0; j2 < 4; j2++) {
                uint32_t bh[4], bl[4];
                uint32_t adr = stg + OFF_BHI + swz(brr + (j2 * 2 + jj) * 8, bcc);
                ldsm4(bh, adr);
                ldsm4(bl, adr + 32768);
                int ja = j2 * 2, jb = ja + 1;
                // 6 groups of 4 independent MMAs: same-acc reuse distance = 8
#pragma unroll
                for (int i = 0; i < 4; i++) mma_bf16(acc[i][ja], ah[i], bh + 0);
#pragma unroll
                for (int i = 0; i < 4; i++) mma_bf16(acc[i][jb], ah[i], bh + 2);
#pragma unroll
                for (int i = 0; i < 4; i++) mma_bf16(acc[i][ja], ah[i], bl + 0);
#pragma unroll
                for (int i = 0; i < 4; i++) mma_bf16(acc[i][jb], ah[i], bl + 2);
#pragma unroll
                for (int i = 0; i < 4; i++) mma_bf16(acc[i][ja], al[i], bh + 0);
#pragma unroll
                for (int i = 0; i < 4; i++) mma_bf16(acc[i][jb], al[i], bh + 2);
            }
        }
        __syncthreads();
        if (c + 2 < nch) { load_chunk(s, c + 2); cpa_commit(); }
    }

    int rb = m0 + wr * 64, cb = n0 + wc * 64;
#pragma unroll
    for (int i = 0; i < 4; i++)
#pragma unroll
        for (int j = 0; j < 8; j++) {
            int r0 = rb + i * 16 + (lane >> 2);
            int c0 = cb + j * 8 + (lane & 3) * 2;
            float bx = bias[c0], by = bias[c0 + 1];
#pragma unroll
            for (int h = 0; h < 2; h++) {
                int row = r0 + h * 8;
                float v0 = acc[i][j][h * 2 + 0] + bx;
                float v1 = acc[i][j][h * 2 + 1] + by;
                size_t o = (size_t)e * sCe + (size_t)row * ldc + c0;
                if (MODE == 0) {
                    v0 = gelu_fast(v0); v1 = gelu_fast(v1);
                    split2(v0, v1, (bf16*)out0 + o, (bf16*)out1 + o);
                } else if (MODE == 1) {
                    *(float2*)((float*)out0 + o) = make_float2(v0, v1);
                } else {
                    size_t oo = (size_t)row * ldc + c0;
                    if (c0 < colmax)     ((float*)out0)[oo] = v0;
                    if (c0 + 1 < colmax) ((float*)out0)[oo + 1] = v1;
                }
            }
        }
}

// ---------------- launch ----------------
extern "C" void kernel_launch(void* const* d_in, const int* in_sizes, int n_in,
                              void* d_out, int out_size) {
    const float* x  = (const float*)d_in[0];
    const float* Wg = (const float*)d_in[1];
    const float* W1 = (const float*)d_in[2];
    const float* b1 = (const float*)d_in[3];
    const float* W2 = (const float*)d_in[4];
    const float* b2 = (const float*)d_in[5];
    const float* Wl = (const float*)d_in[6];
    const float* bl = (const float*)d_in[7];
    float* out = (float*)d_out;

    static int smem_set = 0;
    if (!smem_set) {
        cudaFuncSetAttribute(k_mgemm<0>, cudaFuncAttributeMaxDynamicSharedMemorySize, GEMM_SMEM);
        cudaFuncSetAttribute(k_mgemm<1>, cudaFuncAttributeMaxDynamicSharedMemorySize, GEMM_SMEM);
        cudaFuncSetAttribute(k_mgemm<2>, cudaFuncAttributeMaxDynamicSharedMemorySize, GEMM_SMEM);
        smem_set = 1;
    }

    bf16 *w1h, *w1l, *w2h, *w2l, *wlh, *wll, *dh, *dl, *hh, *hl, *yh, *yl;
    float* oute;
    cudaGetSymbolAddress((void**)&w1h, g_w1t_hi); cudaGetSymbolAddress((void**)&w1l, g_w1t_lo);
    cudaGetSymbolAddress((void**)&w2h, g_w2t_hi); cudaGetSymbolAddress((void**)&w2l, g_w2t_lo);
    cudaGetSymbolAddress((void**)&wlh, g_wlt_hi); cudaGetSymbolAddress((void**)&wll, g_wlt_lo);
    cudaGetSymbolAddress((void**)&dh, g_disp_hi); cudaGetSymbolAddress((void**)&dl, g_disp_lo);
    cudaGetSymbolAddress((void**)&hh, g_h_hi);    cudaGetSymbolAddress((void**)&hl, g_h_lo);
    cudaGetSymbolAddress((void**)&yh, g_y_hi);    cudaGetSymbolAddress((void**)&yl, g_y_lo);
    cudaGetSymbolAddress((void**)&oute, g_oute);

    k_gate<<<NB_GATE, 256>>>(x, Wg);
    k_scan<<<E_NUM, 256>>>();
    k_big<<<BIG_TOT, 256>>>(x, W1, W2, Wl);

    // FFN1 (launch 4 = ncu target)
    k_mgemm<0><<<dim3(H_DIM/256, CAP/128, E_NUM), 256, GEMM_SMEM>>>(
        dh, dl, (size_t)CAP*D_DIM, w1h, w1l, (size_t)H_DIM*D_DIM,
        b1, H_DIM, hh, hl, (size_t)CAP*H_DIM, D_DIM, H_DIM, H_DIM);
    // FFN2
    k_mgemm<1><<<dim3(D_DIM/256, CAP/128, E_NUM), 256, GEMM_SMEM>>>(
        hh, hl, (size_t)CAP*H_DIM, w2h, w2l, (size_t)D_DIM*H_DIM,
        b2, D_DIM, oute, nullptr, (size_t)CAP*D_DIM, H_DIM, D_DIM, D_DIM);

    k_combine<<<N_TOK, 256>>>();

    // classifier
    k_mgemm<2><<<dim3(1024/256, N_TOK/128, 1), 256, GEMM_SMEM>>>(
        yh, yl, 0, wlh, wll, 0,
        bl, 0, out, nullptr, 0, D_DIM, NC_DIM, NC_DIM);

    k_loss<<<1, 32>>>(out, out_size);
}

// round 8
// speedup vs baseline: 2.9684x; 1.0780x over previous
#include <cuda_runtime.h>
#include <cuda_bf16.h>
#include <math.h>
#include <stdint.h>

#define N_TOK 16384
#define D_DIM 1024
#define E_NUM 16
#define H_DIM 4096
#define NC_DIM 1000
#define CAP 2048
#define NB_GATE (N_TOK/8)

typedef __nv_bfloat16 bf16;

// ---------------- device scratch ----------------
__device__ __align__(16) bf16 g_disp_hi[(size_t)E_NUM*CAP*D_DIM];
__device__ __align__(16) bf16 g_disp_lo[(size_t)E_NUM*CAP*D_DIM];
__device__ __align__(16) bf16 g_h_hi[(size_t)E_NUM*CAP*H_DIM];
__device__ __align__(16) bf16 g_h_lo[(size_t)E_NUM*CAP*H_DIM];
__device__ __align__(16) float g_oute[(size_t)E_NUM*CAP*D_DIM];
__device__ __align__(16) bf16 g_y_hi[(size_t)N_TOK*D_DIM];
__device__ __align__(16) bf16 g_y_lo[(size_t)N_TOK*D_DIM];
__device__ __align__(16) bf16 g_w1t_hi[(size_t)E_NUM*H_DIM*D_DIM];
__device__ __align__(16) bf16 g_w1t_lo[(size_t)E_NUM*H_DIM*D_DIM];
__device__ __align__(16) bf16 g_w2t_hi[(size_t)E_NUM*D_DIM*H_DIM];
__device__ __align__(16) bf16 g_w2t_lo[(size_t)E_NUM*D_DIM*H_DIM];
__device__ __align__(16) bf16 g_wlt_hi[(size_t)1024*D_DIM];
__device__ __align__(16) bf16 g_wlt_lo[(size_t)1024*D_DIM];
__device__ int   g_idx[N_TOK];
__device__ float g_gate[N_TOK];
__device__ int   g_lrank[N_TOK];
__device__ int   g_bhist[NB_GATE][E_NUM];
__device__ float g_bprob[NB_GATE][E_NUM];
__device__ int   g_boff[NB_GATE][E_NUM];
__device__ int   g_count[E_NUM];
__device__ float g_probsum[E_NUM];
__device__ int   g_pos[N_TOK];

// ---------------- PTX helpers ----------------
__device__ __forceinline__ uint32_t smem_u32(const void* p) {
    return (uint32_t)__cvta_generic_to_shared(p);
}
__device__ __forceinline__ void cpa(uint32_t dst, const void* src) {
    asm volatile("cp.async.cg.shared.global [%0], [%1], 16;" :: "r"(dst), "l"(src) : "memory");
}
__device__ __forceinline__ void cpa_commit() { asm volatile("cp.async.commit_group;" ::: "memory"); }
template<int N> __device__ __forceinline__ void cpa_wait() {
    asm volatile("cp.async.wait_group %0;" :: "n"(N) : "memory");
}
__device__ __forceinline__ void ldsm4(uint32_t* r, uint32_t a) {
    asm volatile("ldmatrix.sync.aligned.m8n8.x4.shared.b16 {%0,%1,%2,%3}, [%4];"
                 : "=r"(r[0]), "=r"(r[1]), "=r"(r[2]), "=r"(r[3]) : "r"(a));
}
__device__ __forceinline__ void mma_bf16(float* d, const uint32_t* a, const uint32_t* b) {
    asm volatile(
        "mma.sync.aligned.m16n8k16.row.col.f32.bf16.bf16.f32 "
        "{%0,%1,%2,%3}, {%4,%5,%6,%7}, {%8,%9}, {%0,%1,%2,%3};"
        : "+f"(d[0]), "+f"(d[1]), "+f"(d[2]), "+f"(d[3])
        : "r"(a[0]), "r"(a[1]), "r"(a[2]), "r"(a[3]), "r"(b[0]), "r"(b[1]));
}

// ---------------- gating ----------------
__global__ void k_gate(const float* __restrict__ x, const float* __restrict__ Wg) {
    int warp = threadIdx.x >> 5, lane = threadIdx.x & 31;
    int t = blockIdx.x * 8 + warp;
    __shared__ float s_prob[E_NUM];
    __shared__ int s_idx[8];
    if (threadIdx.x < E_NUM) s_prob[threadIdx.x] = 0.f;
    __syncthreads();
    float acc[E_NUM];
#pragma unroll
    for (int e = 0; e < E_NUM; e++) acc[e] = 0.f;
    const float* xr = x + (size_t)t * D_DIM;
    for (int j = 0; j < D_DIM / 32; j++) {
        float xv = xr[lane + 32 * j];
        const float* wr = Wg + (size_t)(lane + 32 * j) * E_NUM;
#pragma unroll
        for (int e = 0; e < E_NUM; e++) acc[e] = fmaf(xv, __ldg(wr + e), acc[e]);
    }
#pragma unroll
    for (int e = 0; e < E_NUM; e++)
#pragma unroll
        for (int o = 16; o > 0; o >>= 1) acc[e] += __shfl_xor_sync(0xffffffffu, acc[e], o);
    if (lane == 0) {
        float m = acc[0]; int ai = 0;
#pragma unroll
        for (int e = 1; e < E_NUM; e++) if (acc[e] > m) { m = acc[e]; ai = e; }
        float p[E_NUM]; float s = 0.f;
#pragma unroll
        for (int e = 0; e < E_NUM; e++) { p[e] = expf(acc[e] - m); s += p[e]; }
        float inv = 1.f / s;
#pragma unroll
        for (int e = 0; e < E_NUM; e++) atomicAdd(&s_prob[e], p[e] * inv);
        g_idx[t] = ai; g_gate[t] = p[ai] * inv; s_idx[warp] = ai;
    }
    __syncthreads();
    if (threadIdx.x == 0) {
        int cnt[E_NUM];
#pragma unroll
        for (int e = 0; e < E_NUM; e++) cnt[e] = 0;
#pragma unroll
        for (int w = 0; w < 8; w++) {
            int e = s_idx[w];
            g_lrank[blockIdx.x * 8 + w] = cnt[e];
            cnt[e]++;
        }
#pragma unroll
        for (int e = 0; e < E_NUM; e++) g_bhist[blockIdx.x][e] = cnt[e];
    }
    if (threadIdx.x < E_NUM) g_bprob[blockIdx.x][threadIdx.x] = s_prob[threadIdx.x];
}

// ---------------- scan + probsum reduce + pad ----------------
__global__ void k_scan() {
    const int PB = NB_GATE / 256;
    int e = blockIdx.x, tid = threadIdx.x;
    int v[PB]; int s = 0;
    float ps = 0.f;
#pragma unroll
    for (int i = 0; i < PB; i++) {
        v[i] = g_bhist[tid * PB + i][e];
        s += v[i];
        ps += g_bprob[tid * PB + i][e];
    }
    __shared__ int sh[256];
    __shared__ float sp[256];
    sh[tid] = s; sp[tid] = ps;
    __syncthreads();
    for (int o = 1; o < 256; o <<= 1) {
        int q = (tid >= o) ? sh[tid - o] : 0;
        __syncthreads(); sh[tid] += q; __syncthreads();
    }
    int off = sh[tid] - s;
#pragma unroll
    for (int i = 0; i < PB; i++) { g_boff[tid * PB + i][e] = off; off += v[i]; }
    for (int o = 128; o > 0; o >>= 1) {
        if (tid < o) sp[tid] += sp[tid + o];
        __syncthreads();
    }
    if (tid == 0) { g_count[e] = sh[255]; g_probsum[e] = sp[0]; }
    __syncthreads();
    int c = sh[255]; if (c > CAP) c = CAP;
    int r1 = (c + 127) & ~127; if (r1 > CAP) r1 = CAP;
    for (int r = c; r < r1; r++) {
        size_t b = ((size_t)e * CAP + r) * D_DIM + tid * 4;
        *(float2*)(g_disp_hi + b) = make_float2(0.f, 0.f);
        *(float2*)(g_disp_lo + b) = make_float2(0.f, 0.f);
    }
}

__device__ __forceinline__ void split2(float a, float b, bf16* hi, bf16* lo) {
    bf16 ha = __float2bfloat16(a), hb = __float2bfloat16(b);
    *(__nv_bfloat162*)hi = __halves2bfloat162(ha, hb);
    *(__nv_bfloat162*)lo = __halves2bfloat162(
        __float2bfloat16(a - __bfloat162float(ha)),
        __float2bfloat16(b - __bfloat162float(hb)));
}

// wsplit body: in [E,R,C] fp32 -> out [E,Cpad,R] bf16 hi/lo
__device__ __forceinline__ void wsplit_body(
    const float* __restrict__ in, bf16* __restrict__ ohi, bf16* __restrict__ olo,
    int R, int C, int Cpad, int bx, int by, int bz, int tid)
{
    __shared__ float s[32][33];
    const float* ip = in + (size_t)bz * R * C;
    size_t ob = (size_t)bz * Cpad * R;
    int c0 = bx * 32, r0 = by * 32;
    int tx = tid & 31, ty = tid >> 5;
#pragma unroll
    for (int k = 0; k < 4; k++) {
        int r = r0 + ty + 8 * k, c = c0 + tx;
        s[ty + 8 * k][tx] = (c < C) ? ip[(size_t)r * C + c] : 0.f;
    }
    __syncthreads();
#pragma unroll
    for (int k = 0; k < 4; k++) {
        int cc = ty + 8 * k;
        float v = s[tx][cc];
        bf16 h = __float2bfloat16(v);
        size_t o = ob + (size_t)(c0 + cc) * R + r0 + tx;
        ohi[o] = h;
        olo[o] = __float2bfloat16(v - __bfloat162float(h));
    }
}

#define BIG_W1 16384
#define BIG_W2 (16384 + 65536)
#define BIG_WL (16384 + 2*65536)
#define BIG_TOT (16384 + 2*65536 + 1024)

__global__ void k_big(const float* __restrict__ x, const float* __restrict__ W1,
                      const float* __restrict__ W2, const float* __restrict__ Wl) {
    int b = blockIdx.x, tid = threadIdx.x;
    if (b < BIG_W1) {
        int t = b;
        int e = g_idx[t];
        int pos = g_boff[t >> 3][e] + g_lrank[t];
        if (pos < CAP) {
            if (tid == 0) g_pos[t] = pos;
            float4 v = ((const float4*)(x + (size_t)t * D_DIM))[tid];
            size_t o = ((size_t)e * CAP + pos) * D_DIM + tid * 4;
            split2(v.x, v.y, g_disp_hi + o, g_disp_lo + o);
            split2(v.z, v.w, g_disp_hi + o + 2, g_disp_lo + o + 2);
        } else if (tid == 0) g_pos[t] = -1;
    } else if (b < BIG_W2) {
        int i = b - BIG_W1;
        int bx = i % 128, by = (i / 128) % 32, bz = i / (128 * 32);
        wsplit_body(W1, g_w1t_hi, g_w1t_lo, D_DIM, H_DIM, H_DIM, bx, by, bz, tid);
    } else if (b < BIG_WL) {
        int i = b - BIG_W2;
        int bx = i % 32, by = (i / 32) % 128, bz = i / (32 * 128);
        wsplit_body(W2, g_w2t_hi, g_w2t_lo, H_DIM, D_DIM, D_DIM, bx, by, bz, tid);
    } else {
        int i = b - BIG_WL;
        int bx = i % 32, by = i / 32;
        wsplit_body(Wl, g_wlt_hi, g_wlt_lo, D_DIM, NC_DIM, 1024, bx, by, 0, tid);
    }
}

__global__ void k_combine() {
    int t = blockIdx.x;
    int pos = g_pos[t];
    size_t b = (size_t)t * D_DIM + threadIdx.x * 4;
    if (pos >= 0) {
        int e = g_idx[t];
        float g = g_gate[t];
        float4 v = ((const float4*)(g_oute + ((size_t)e * CAP + pos) * D_DIM))[threadIdx.x];
        split2(v.x * g, v.y * g, g_y_hi + b, g_y_lo + b);
        split2(v.z * g, v.w * g, g_y_hi + b + 2, g_y_lo + b + 2);
    } else {
        *(float2*)(g_y_hi + b) = make_float2(0.f, 0.f);
        *(float2*)(g_y_lo + b) = make_float2(0.f, 0.f);
    }
}

__global__ void k_loss(float* out, int out_size) {
    if (out_size <= N_TOK * NC_DIM) return;
    if (threadIdx.x == 0 && blockIdx.x == 0) {
        float s = 0.f;
        for (int e = 0; e < E_NUM; e++)
            s += ((float)g_count[e] / (float)N_TOK) * (g_probsum[e] / (float)N_TOK);
        out[(size_t)N_TOK * NC_DIM] = s * (float)E_NUM;
    }
}

// ------------- mma.sync bf16 GEMM: CTA 128xNT, BK=64, 2-stage, 1 sync/chunk
// WI=4: NT=256, 8 warps 2x4, warp 64x64.  WI=2: NT=128, 8 warps 4x2, warp 32x64.
#define OFF_ALO 16384
#define OFF_BHI 32768

__device__ __forceinline__ float gelu_fast(float v) {
    float u = 0.7978845608028654f * (v + 0.044715f * v * v * v);
    float t;
    asm("tanh.approx.f32 %0, %1;" : "=f"(t) : "f"(u));
    return 0.5f * v * (1.f + t);
}
__device__ __forceinline__ uint32_t swz(int row, int c) {
    return (uint32_t)(row * 128 + ((c ^ (row & 7)) << 4));
}

template <int MODE, int WI>
__global__ void __launch_bounds__(256, 1) k_mgemm(
    const bf16* __restrict__ Ahi, const bf16* __restrict__ Alo, size_t sAe,
    const bf16* __restrict__ Bhi, const bf16* __restrict__ Blo, size_t sBe,
    const float* __restrict__ bias, int sBiasE,
    void* __restrict__ out0, void* __restrict__ out1, size_t sCe,
    int K, int ldc, int colmax)
{
    constexpr int NT = WI * 64;                 // 256 or 128
    constexpr int OFF_BLO = OFF_BHI + NT * 128;
    constexpr int STGB = OFF_BHI + 2 * NT * 128;

    int e = blockIdx.z;
    int m0 = blockIdx.y * 128, n0 = blockIdx.x * NT;
    if (MODE < 2) {
        int c = g_count[e]; if (c > CAP) c = CAP;
        if (m0 >= c) return;
    }
    Ahi += (size_t)e * sAe; Alo += (size_t)e * sAe;
    Bhi += (size_t)e * sBe; Blo += (size_t)e * sBe;
    bias += (size_t)e * sBiasE;

    extern __shared__ char smem_raw[];
    uint32_t base = (smem_u32(smem_raw) + 127) & ~127u;

    int tid = threadIdx.x, lane = tid & 31, wid = tid >> 5;
    int wm, wn;
    if (WI == 4) { wm = (wid >> 2) * 64; wn = (wid & 3) * 64; }
    else         { wm = (wid >> 1) * 32; wn = (wid & 1) * 64; }

    float acc[WI][8][4];
#pragma unroll
    for (int i = 0; i < WI; i++)
#pragma unroll
        for (int j = 0; j < 8; j++)
#pragma unroll
            for (int q = 0; q < 4; q++) acc[i][j][q] = 0.f;

    int nch = K >> 6;

    auto load_a = [&](int s, int c) {
        if (c >= nch) return;
        uint32_t stg = base + s * STGB;
        int k0 = c << 6;
#pragma unroll
        for (int it = 0; it < 4; it++) {
            int i = tid + it * 256;
            int row = i >> 3, cc = i & 7;
            uint32_t o = swz(row, cc);
            size_t gi = (size_t)(m0 + row) * K + k0 + cc * 8;
            cpa(stg + o, Ahi + gi);
            cpa(stg + OFF_ALO + o, Alo + gi);
        }
    };
    auto load_bh = [&](int s, int c) {
        if (c >= nch) return;
        uint32_t stg = base + s * STGB;
        int k0 = c << 6;
#pragma unroll
        for (int it = 0; it < NT / 32; it++) {
            int i = tid + it * 256;
            int row = i >> 3, cc = i & 7;
            size_t gi = (size_t)(n0 + row) * K + k0 + cc * 8;
            cpa(stg + OFF_BHI + swz(row, cc), Bhi + gi);
        }
    };
    auto load_bl = [&](int s, int c) {
        if (c >= nch) return;
        uint32_t stg = base + s * STGB;
        int k0 = c << 6;
#pragma unroll
        for (int it = 0; it < NT / 32; it++) {
            int i = tid + it * 256;
            int row = i >> 3, cc = i & 7;
            size_t gi = (size_t)(n0 + row) * K + k0 + cc * 8;
            cpa(stg + OFF_BLO + swz(row, cc), Blo + gi);
        }
    };

    auto compute_ks = [&](int ks, uint32_t stg) {
        uint32_t ah[WI][4], al[WI][4];
        int ar = wm + (lane & 15);
        int ac = ks * 2 + (lane >> 4);
#pragma unroll
        for (int i = 0; i < WI; i++) {
            uint32_t adr = stg + swz(ar + i * 16, ac);
            ldsm4(ah[i], adr);
            ldsm4(al[i], adr + OFF_ALO);
        }
        int jj = (lane >> 4);
        int brr = wn + (lane & 7);
        int bcc = ks * 2 + ((lane >> 3) & 1);
#pragma unroll
        for (int j2 = 0; j2 < 4; j2++) {
            uint32_t bh[4], bl[4];
            uint32_t adr = stg + OFF_BHI + swz(brr + (j2 * 2 + jj) * 8, bcc);
            ldsm4(bh, adr);
            ldsm4(bl, adr + NT * 128);
            int ja = j2 * 2, jb = ja + 1;
#pragma unroll
            for (int i = 0; i < WI; i++) mma_bf16(acc[i][ja], ah[i], bh + 0);
#pragma unroll
            for (int i = 0; i < WI; i++) mma_bf16(acc[i][jb], ah[i], bh + 2);
#pragma unroll
            for (int i = 0; i < WI; i++) mma_bf16(acc[i][ja], ah[i], bl + 0);
#pragma unroll
            for (int i = 0; i < WI; i++) mma_bf16(acc[i][jb], ah[i], bl + 2);
#pragma unroll
            for (int i = 0; i < WI; i++) mma_bf16(acc[i][ja], al[i], bh + 0);
#pragma unroll
            for (int i = 0; i < WI; i++) mma_bf16(acc[i][jb], al[i], bh + 2);
        }
    };

    // prologue: chunk 0 into stage 0
    load_a(0, 0); load_bh(0, 0); load_bl(0, 0); cpa_commit();

    for (int c = 0; c < nch; c++) {
        int s = c & 1;
        uint32_t stg = base + s * STGB;
        cpa_wait<0>();
        __syncthreads();
        compute_ks(0, stg);
        load_a(s ^ 1, c + 1);
        load_bh(s ^ 1, c + 1);
        compute_ks(1, stg);
        load_bl(s ^ 1, c + 1);
        cpa_commit();
        compute_ks(2, stg);
        compute_ks(3, stg);
    }

    int rb = m0 + wm, cb = n0 + wn;
#pragma unroll
    for (int i = 0; i < WI; i++)
#pragma unroll
        for (int j = 0; j < 8; j++) {
            int r0 = rb + i * 16 + (lane >> 2);
            int c0 = cb + j * 8 + (lane & 3) * 2;
            float bx = bias[c0], by = bias[c0 + 1];
#pragma unroll
            for (int h = 0; h < 2; h++) {
                int row = r0 + h * 8;
                float v0 = acc[i][j][h * 2 + 0] + bx;
                float v1 = acc[i][j][h * 2 + 1] + by;
                size_t o = (size_t)e * sCe + (size_t)row * ldc + c0;
                if (MODE == 0) {
                    v0 = gelu_fast(v0); v1 = gelu_fast(v1);
                    split2(v0, v1, (bf16*)out0 + o, (bf16*)out1 + o);
                } else if (MODE == 1) {
                    *(float2*)((float*)out0 + o) = make_float2(v0, v1);
                } else {
                    size_t oo = (size_t)row * ldc + c0;
                    if (c0 < colmax)     ((float*)out0)[oo] = v0;
                    if (c0 + 1 < colmax) ((float*)out0)[oo + 1] = v1;
                }
            }
        }
}

// ---------------- launch ----------------
extern "C" void kernel_launch(void* const* d_in, const int* in_sizes, int n_in,
                              void* d_out, int out_size) {
    const float* x  = (const float*)d_in[0];
    const float* Wg = (const float*)d_in[1];
    const float* W1 = (const float*)d_in[2];
    const float* b1 = (const float*)d_in[3];
    const float* W2 = (const float*)d_in[4];
    const float* b2 = (const float*)d_in[5];
    const float* Wl = (const float*)d_in[6];
    const float* bl = (const float*)d_in[7];
    float* out = (float*)d_out;

    const int SMEM_BIG = 32768 + 2 * 256 * 128 + 128;   // 98432 for WI=4 stage... (2 stages)
    const int GEMM_SMEM4 = 2 * (32768 + 2 * 256 * 128) + 128;  // 196736
    const int GEMM_SMEM2 = 2 * (32768 + 2 * 128 * 128) + 128;  // 131200
    (void)SMEM_BIG;

    static int smem_set = 0;
    if (!smem_set) {
        cudaFuncSetAttribute((const void*)k_mgemm<0,4>, cudaFuncAttributeMaxDynamicSharedMemorySize, GEMM_SMEM4);
        cudaFuncSetAttribute((const void*)k_mgemm<1,4>, cudaFuncAttributeMaxDynamicSharedMemorySize, GEMM_SMEM4);
        cudaFuncSetAttribute((const void*)k_mgemm<2,2>, cudaFuncAttributeMaxDynamicSharedMemorySize, GEMM_SMEM2);
        smem_set = 1;
    }

    bf16 *w1h, *w1l, *w2h, *w2l, *wlh, *wll, *dh, *dl, *hh, *hl, *yh, *yl;
    float* oute;
    cudaGetSymbolAddress((void**)&w1h, g_w1t_hi); cudaGetSymbolAddress((void**)&w1l, g_w1t_lo);
    cudaGetSymbolAddress((void**)&w2h, g_w2t_hi); cudaGetSymbolAddress((void**)&w2l, g_w2t_lo);
    cudaGetSymbolAddress((void**)&wlh, g_wlt_hi); cudaGetSymbolAddress((void**)&wll, g_wlt_lo);
    cudaGetSymbolAddress((void**)&dh, g_disp_hi); cudaGetSymbolAddress((void**)&dl, g_disp_lo);
    cudaGetSymbolAddress((void**)&hh, g_h_hi);    cudaGetSymbolAddress((void**)&hl, g_h_lo);
    cudaGetSymbolAddress((void**)&yh, g_y_hi);    cudaGetSymbolAddress((void**)&yl, g_y_lo);
    cudaGetSymbolAddress((void**)&oute, g_oute);

    k_gate<<<NB_GATE, 256>>>(x, Wg);
    k_scan<<<E_NUM, 256>>>();
    k_big<<<BIG_TOT, 256>>>(x, W1, W2, Wl);

    // FFN1 (launch 4 = ncu target): [CAP,1024] x [4096,1024]^T -> h bf16 hi/lo
    k_mgemm<0,4><<<dim3(H_DIM/256, CAP/128, E_NUM), 256, GEMM_SMEM4>>>(
        dh, dl, (size_t)CAP*D_DIM, w1h, w1l, (size_t)H_DIM*D_DIM,
        b1, H_DIM, hh, hl, (size_t)CAP*H_DIM, D_DIM, H_DIM, H_DIM);
    // FFN2: [CAP,4096] x [1024,4096]^T -> oute f32
    k_mgemm<1,4><<<dim3(D_DIM/256, CAP/128, E_NUM), 256, GEMM_SMEM4>>>(
        hh, hl, (size_t)CAP*H_DIM, w2h, w2l, (size_t)D_DIM*H_DIM,
        b2, D_DIM, oute, nullptr, (size_t)CAP*D_DIM, H_DIM, D_DIM, D_DIM);

    k_combine<<<N_TOK, 256>>>();

    // classifier (NT=128 tiles): [16384,1024] x [1024,1024]^T -> out [16384,1000]
    k_mgemm<2,2><<<dim3(1024/128, N_TOK/128, 1), 256, GEMM_SMEM2>>>(
        yh, yl, 0, wlh, wll, 0,
        bl, 0, out, nullptr, 0, D_DIM, NC_DIM, NC_DIM);

    k_loss<<<1, 32>>>(out, out_size);
}